// round 13
// baseline (speedup 1.0000x reference)
#include <cuda_runtime.h>
#include <cuda_bf16.h>
#include <stdint.h>
#include <math.h>

// Problem constants
#define B_   2
#define S_   2048
#define D_   1024
#define H_   16
#define HD_  64
#define M_TOT (B_*S_)     // 4096
#define N_QKV (3*D_)      // 3072

#define N_GEMM_BLKS  768          // 32 m-tiles x 24 n-tiles
#define N_ATTN_BLKS  512          // 16 q-tiles x 32 bh

// ---------------------------------------------------------------------------
// Scratch (allocation-free rule: __device__ globals)
// ---------------------------------------------------------------------------
__device__ __nv_bfloat16 g_x_hi [(size_t)M_TOT * D_];
__device__ __nv_bfloat16 g_x_lo [(size_t)M_TOT * D_];
__device__ __nv_bfloat16 g_wq_hi[(size_t)N_QKV * D_];
__device__ __nv_bfloat16 g_wq_lo[(size_t)N_QKV * D_];
__device__ __nv_bfloat16 g_at_hi[(size_t)M_TOT * D_];
__device__ __nv_bfloat16 g_at_lo[(size_t)M_TOT * D_];
__device__ __nv_bfloat16 g_wo_hi[(size_t)D_ * D_];
__device__ __nv_bfloat16 g_wo_lo[(size_t)D_ * D_];

__device__ __nv_bfloat16 g_aq_hi [(size_t)B_*H_*S_*HD_];
__device__ __nv_bfloat16 g_aq_lo [(size_t)B_*H_*S_*HD_];
__device__ __nv_bfloat16 g_ak_hi [(size_t)B_*H_*S_*HD_];
__device__ __nv_bfloat16 g_ak_lo [(size_t)B_*H_*S_*HD_];
__device__ __nv_bfloat16 g_avt_hi[(size_t)B_*H_*HD_*S_];
__device__ __nv_bfloat16 g_avt_lo[(size_t)B_*H_*HD_*S_];

// per-row-tile completion counters (row tile = 128 tokens); 24 n-blocks each
__device__ int g_tile_cnt[32];

__global__ void zero_cnt() { if (threadIdx.x < 32) g_tile_cnt[threadIdx.x] = 0; }

// ---------------------------------------------------------------------------
// helpers
// ---------------------------------------------------------------------------
__device__ __forceinline__ uint32_t pack_bf2(float lo, float hi) {
    __nv_bfloat162 t = __floats2bfloat162_rn(lo, hi);
    return *(uint32_t*)&t;
}
__device__ __forceinline__ void split1(float v, float& h, float& l) {
    __nv_bfloat16 hb = __float2bfloat16_rn(v);
    h = __bfloat162float(hb);
    l = v - h;
}
__device__ __forceinline__ void mma16816(float* c, const uint32_t* a, const uint32_t* b)
{
    asm volatile(
        "mma.sync.aligned.m16n8k16.row.col.f32.bf16.bf16.f32 "
        "{%0,%1,%2,%3}, {%4,%5,%6,%7}, {%8,%9}, {%0,%1,%2,%3};\n"
        : "+f"(c[0]), "+f"(c[1]), "+f"(c[2]), "+f"(c[3])
        : "r"(a[0]), "r"(a[1]), "r"(a[2]), "r"(a[3]), "r"(b[0]), "r"(b[1]));
}
__device__ __forceinline__ void ldsm_x4(uint32_t* r, uint32_t addr)
{
    asm volatile(
        "ldmatrix.sync.aligned.m8n8.x4.shared.b16 {%0,%1,%2,%3}, [%4];\n"
        : "=r"(r[0]), "=r"(r[1]), "=r"(r[2]), "=r"(r[3]) : "r"(addr));
}

// ---------------------------------------------------------------------------
// Elementwise split for GEMM inputs
// ---------------------------------------------------------------------------
template<int ID>
__global__ void split_bf16(const float* __restrict__ src, int n4)
{
    __nv_bfloat16* hi = (ID == 0) ? g_x_hi : (ID == 1) ? g_wq_hi : g_wo_hi;
    __nv_bfloat16* lo = (ID == 0) ? g_x_lo : (ID == 1) ? g_wq_lo : g_wo_lo;

    for (int i = blockIdx.x * blockDim.x + threadIdx.x; i < n4;
         i += gridDim.x * blockDim.x) {
        float4 v = ((const float4*)src)[i];
        float h0,l0,h1,l1,h2,l2,h3,l3;
        split1(v.x,h0,l0); split1(v.y,h1,l1); split1(v.z,h2,l2); split1(v.w,h3,l3);
        ((uint32_t*)hi)[2*i + 0] = pack_bf2(h0, h1);
        ((uint32_t*)hi)[2*i + 1] = pack_bf2(h2, h3);
        ((uint32_t*)lo)[2*i + 0] = pack_bf2(l0, l1);
        ((uint32_t*)lo)[2*i + 1] = pack_bf2(l2, l3);
    }
}

// ---------------------------------------------------------------------------
// Layout constants
// ---------------------------------------------------------------------------
#define GLDW 20
#define GARR (128 * GLDW)
#define GSTG (4 * GARR)
#define GEMM_SMEM_BYTES (2 * GSTG * 4)   // 81920

#define ROW_W   36
#define ARR_W   (64 * ROW_W)
#define BUF_W   (4 * ARR_W)
#define ATTN_SMEM_BYTES (2 * BUF_W * 4)  // 73728

#define FUSED_SMEM_BYTES GEMM_SMEM_BYTES // max of the two

// ---------------------------------------------------------------------------
// FUSED kernel: blocks [0,768) = QKV-projection tiles (producer, row-ordered
// with batches interleaved); blocks [768,1280) = causal attention (consumer,
// ascending q-tile so deps are ready early and tails overlap).
// ---------------------------------------------------------------------------
__global__ void fused_qkv_attn()
{
    extern __shared__ uint32_t smw[];
    const int bid = blockIdx.x;
    const int tid = threadIdx.x;
    const uint32_t sb = (uint32_t)__cvta_generic_to_shared(smw);

    if (bid < N_GEMM_BLKS) {
        // ================= GEMM producer =================
        const int seq    = bid / 24;
        const int m_tile = (seq & 1) ? (16 + (seq >> 1)) : (seq >> 1);  // interleave batches
        const int n_tile = bid - seq * 24;
        const int bm = m_tile * 128;
        const int bn = n_tile * 128;
        const int K  = D_;

        const __nv_bfloat16 *Ah = g_x_hi, *Al = g_x_lo, *Bh = g_wq_hi, *Bl = g_wq_lo;

        const int lane = tid & 31;
        const int warp = tid >> 5;
        const int wr = warp >> 1, wc = warp & 1;
        const int gid = lane >> 2, tig = lane & 3;
        const int lrow   = tid >> 2;
        const int lchunk = tid & 3;

        #define G_LOAD(T, S) do {                                                   \
            int k0_ = (T) * 32;                                                     \
            _Pragma("unroll")                                                       \
            for (int hh = 0; hh < 2; hh++) {                                        \
                int row = lrow + hh * 64;                                           \
                uint32_t d0 = sb + (uint32_t)((S)*GSTG + row*GLDW + lchunk*4) * 4;  \
                size_t asrc = (size_t)(bm + row) * K + k0_ + lchunk*8;              \
                size_t bsrc = (size_t)(bn + row) * K + k0_ + lchunk*8;              \
                asm volatile("cp.async.cg.shared.global [%0], [%1], 16;\n"          \
                    :: "r"(d0),              "l"(Ah + asrc));                       \
                asm volatile("cp.async.cg.shared.global [%0], [%1], 16;\n"          \
                    :: "r"(d0 + GARR*4),     "l"(Al + asrc));                       \
                asm volatile("cp.async.cg.shared.global [%0], [%1], 16;\n"          \
                    :: "r"(d0 + 2*GARR*4),   "l"(Bh + bsrc));                       \
                asm volatile("cp.async.cg.shared.global [%0], [%1], 16;\n"          \
                    :: "r"(d0 + 3*GARR*4),   "l"(Bl + bsrc));                       \
            }                                                                       \
            asm volatile("cp.async.commit_group;\n");                               \
        } while (0)

        uint32_t a_off[2], b_off[4];
        #pragma unroll
        for (int mi = 0; mi < 2; mi++)
            a_off[mi] = (uint32_t)((wr*32 + mi*16 + (lane & 15)) * GLDW * 4
                                   + (lane >> 4) * 16);
        #pragma unroll
        for (int np = 0; np < 4; np++)
            b_off[np] = (uint32_t)((wc*64 + np*16 + ((lane >> 4) & 1)*8 + (lane & 7))
                                   * GLDW * 4 + ((lane >> 3) & 1) * 16);

        float acc[2][8][4] = {};

        const int nt = K / 32;
        G_LOAD(0, 0);

        for (int t = 0; t < nt; t++) {
            const int stg = t & 1;
            if (t + 1 < nt) {
                G_LOAD(t + 1, (t + 1) & 1);
                asm volatile("cp.async.wait_group 1;\n");
            } else {
                asm volatile("cp.async.wait_group 0;\n");
            }
            __syncthreads();

            const uint32_t sAh = sb + (uint32_t)(stg * GSTG) * 4;
            const uint32_t sAl = sAh + GARR * 4;
            const uint32_t sBh = sAh + 2 * GARR * 4;
            const uint32_t sBl = sAh + 3 * GARR * 4;

            #pragma unroll
            for (int kcb = 0; kcb < 2; kcb++) {
                uint32_t ah[2][4], al[2][4];
                ldsm_x4(ah[0], sAh + a_off[0] + kcb*32);
                ldsm_x4(ah[1], sAh + a_off[1] + kcb*32);
                ldsm_x4(al[0], sAl + a_off[0] + kcb*32);
                ldsm_x4(al[1], sAl + a_off[1] + kcb*32);
                #pragma unroll
                for (int np = 0; np < 4; np++) {
                    uint32_t bhf[4], blf[4];
                    ldsm_x4(bhf, sBh + b_off[np] + kcb*32);
                    ldsm_x4(blf, sBl + b_off[np] + kcb*32);
                    #pragma unroll
                    for (int term = 0; term < 3; term++) {
                        #pragma unroll
                        for (int sub = 0; sub < 2; sub++) {
                            #pragma unroll
                            for (int mi = 0; mi < 2; mi++) {
                                int ni = np * 2 + sub;
                                if      (term == 0) mma16816(acc[mi][ni], ah[mi], bhf + sub*2);
                                else if (term == 1) mma16816(acc[mi][ni], ah[mi], blf + sub*2);
                                else                mma16816(acc[mi][ni], al[mi], bhf + sub*2);
                            }
                        }
                    }
                }
            }
            __syncthreads();
        }
        #undef G_LOAD

        // Fused qkv-repack epilogue
        #pragma unroll
        for (int mi = 0; mi < 2; mi++) {
            const int row  = bm + wr * 32 + mi * 16 + gid;
            const int bidx = row >> 11;
            const int tokA = row & 2047;
            const int tokB = tokA + 8;
            #pragma unroll
            for (int ni = 0; ni < 8; ni++) {
                int col = bn + wc * 64 + ni * 8 + tig * 2;
                int h   = col / 192;
                int r   = col - h * 192;
                int bh  = bidx * H_ + h;
                float v0 = acc[mi][ni][0], v1 = acc[mi][ni][1];
                float v2 = acc[mi][ni][2], v3 = acc[mi][ni][3];
                float h0,l0,h1,l1,h2,l2,h3,l3;
                if (r < 128) {
                    __nv_bfloat16 *dh, *dl;
                    int d;
                    if (r < 64) {
                        d = r;
                        v0 *= (1.0f/HD_); v1 *= (1.0f/HD_);
                        v2 *= (1.0f/HD_); v3 *= (1.0f/HD_);
                        dh = g_aq_hi; dl = g_aq_lo;
                    } else {
                        d = r - 64;
                        dh = g_ak_hi; dl = g_ak_lo;
                    }
                    split1(v0,h0,l0); split1(v1,h1,l1);
                    split1(v2,h2,l2); split1(v3,h3,l3);
                    size_t i0 = ((size_t)bh * S_ + tokA) * HD_ + d;
                    size_t i1 = ((size_t)bh * S_ + tokB) * HD_ + d;
                    *(uint32_t*)(dh + i0) = pack_bf2(h0, h1);
                    *(uint32_t*)(dl + i0) = pack_bf2(l0, l1);
                    *(uint32_t*)(dh + i1) = pack_bf2(h2, h3);
                    *(uint32_t*)(dl + i1) = pack_bf2(l2, l3);
                } else {
                    int d = r - 128;
                    split1(v0,h0,l0); split1(v1,h1,l1);
                    split1(v2,h2,l2); split1(v3,h3,l3);
                    size_t r0 = ((size_t)bh * HD_ + d)     * S_;
                    size_t r1 = ((size_t)bh * HD_ + d + 1) * S_;
                    g_avt_hi[r0 + tokA] = __float2bfloat16_rn(h0);
                    g_avt_hi[r1 + tokA] = __float2bfloat16_rn(h1);
                    g_avt_hi[r0 + tokB] = __float2bfloat16_rn(h2);
                    g_avt_hi[r1 + tokB] = __float2bfloat16_rn(h3);
                    g_avt_lo[r0 + tokA] = __float2bfloat16_rn(l0);
                    g_avt_lo[r1 + tokA] = __float2bfloat16_rn(l1);
                    g_avt_lo[r0 + tokB] = __float2bfloat16_rn(l2);
                    g_avt_lo[r1 + tokB] = __float2bfloat16_rn(l3);
                }
            }
        }

        // release: make tile writes visible, then bump the row-tile counter
        __threadfence();
        __syncthreads();
        if (tid == 0) atomicAdd(&g_tile_cnt[m_tile], 1);

    } else {
        // ================= Attention consumer =================
        const int aid = bid - N_GEMM_BLKS;
        const int bx  = aid >> 5;          // ascending: deps-earliest first
        const int bh  = aid & 31;
        const int b   = bh >> 4;
        const int h   = bh & 15;

        const int w    = tid >> 5, lane = tid & 31;
        const int gid  = lane >> 2, tig = lane & 3;
        const int rA   = bx * 128 + w * 16 + gid;
        const int rB   = rA + 8;

        // dependency tracker: row tiles (within batch) needed in increasing order
        int ready_m = -1;
        #define ENSURE(MT) do {                                                   \
            if ((MT) > ready_m) {                                                 \
                if (tid == 0) {                                                   \
                    while (((volatile int*)g_tile_cnt)[b * 16 + (MT)] < 24)       \
                        __nanosleep(128);                                         \
                }                                                                 \
                __syncthreads();                                                  \
                __threadfence();                                                  \
                ready_m = (MT);                                                   \
            }                                                                     \
        } while (0)

        ENSURE(bx);   // Q tile (also implies nothing else yet)

        const uint32_t* qh_p = (const uint32_t*)(g_aq_hi + ((size_t)bh * S_ + bx*128 + w*16) * HD_);
        const uint32_t* ql_p = (const uint32_t*)(g_aq_lo + ((size_t)bh * S_ + bx*128 + w*16) * HD_);
        uint32_t qh[4][4], ql[4][4];
        #pragma unroll
        for (int kc = 0; kc < 4; kc++) {
            int w0 = 8*kc + tig;
            qh[kc][0] = qh_p[ gid      * 32 + w0    ];
            qh[kc][1] = qh_p[(gid + 8) * 32 + w0    ];
            qh[kc][2] = qh_p[ gid      * 32 + w0 + 4];
            qh[kc][3] = qh_p[(gid + 8) * 32 + w0 + 4];
            ql[kc][0] = ql_p[ gid      * 32 + w0    ];
            ql[kc][1] = ql_p[(gid + 8) * 32 + w0    ];
            ql[kc][2] = ql_p[ gid      * 32 + w0 + 4];
            ql[kc][3] = ql_p[(gid + 8) * 32 + w0 + 4];
        }
        ready_m = -1;  // re-check KV tiles from 0 (counters monotonic; cheap)

        float o[8][4] = {};
        float mA = -INFINITY, mB = -INFINITY, lA = 0.f, lB = 0.f;

        const __nv_bfloat16* kh_p = g_ak_hi  + (size_t)bh * S_ * HD_;
        const __nv_bfloat16* kl_p = g_ak_lo  + (size_t)bh * S_ * HD_;
        const __nv_bfloat16* vh_p = g_avt_hi + (size_t)bh * HD_ * S_;
        const __nv_bfloat16* vl_p = g_avt_lo + (size_t)bh * HD_ * S_;

        const int lr  = tid >> 3;
        const int seg = tid & 7;
        const uint32_t frag_off = (uint32_t)((lane & 7) * ROW_W * 4 + (lane >> 3) * 16);

        #define LOAD_KV(T, BUF) do {                                                \
            _Pragma("unroll")                                                       \
            for (int i = 0; i < 8; i++) {                                           \
                int arr = i >> 1;                                                   \
                int r   = (i & 1) * 32 + lr;                                        \
                uint32_t dst = sb + ((BUF)*BUF_W + arr*ARR_W + r*ROW_W + seg*4)*4;  \
                const __nv_bfloat16* srcp;                                          \
                if      (arr == 0) srcp = kh_p + (size_t)((T)*64 + r) * HD_ + seg*8;\
                else if (arr == 1) srcp = kl_p + (size_t)((T)*64 + r) * HD_ + seg*8;\
                else if (arr == 2) srcp = vh_p + (size_t)r * S_ + (T)*64 + seg*8;   \
                else               srcp = vl_p + (size_t)r * S_ + (T)*64 + seg*8;   \
                asm volatile("cp.async.cg.shared.global [%0], [%1], 16;\n"          \
                    :: "r"(dst), "l"(srcp));                                        \
            }                                                                       \
            asm volatile("cp.async.commit_group;\n");                               \
        } while (0)

        #define MMA_PAIR(ACC0, ACC1, AH, AL, F0H, F0L, F1H, F1L, KP) do {           \
            mma16816(ACC0, AH[2*(KP)],   F0H);     mma16816(ACC1, AH[2*(KP)],   F1H);     \
            mma16816(ACC0, AH[2*(KP)],   F0L);     mma16816(ACC1, AH[2*(KP)],   F1L);     \
            mma16816(ACC0, AL[2*(KP)],   F0H);     mma16816(ACC1, AL[2*(KP)],   F1H);     \
            mma16816(ACC0, AH[2*(KP)+1], F0H + 2); mma16816(ACC1, AH[2*(KP)+1], F1H + 2); \
            mma16816(ACC0, AH[2*(KP)+1], F0L + 2); mma16816(ACC1, AH[2*(KP)+1], F1L + 2); \
            mma16816(ACC0, AL[2*(KP)+1], F0H + 2); mma16816(ACC1, AL[2*(KP)+1], F1H + 2); \
        } while (0)

        const int nt = 2 * (bx + 1);
        ENSURE(0);
        LOAD_KV(0, 0);

        for (int t = 0; t < nt; t++) {
            const int buf = t & 1;
            if (t + 1 < nt) {
                ENSURE((t + 1) >> 1);
                LOAD_KV(t + 1, (t + 1) & 1);
                asm volatile("cp.async.wait_group 1;\n");
            } else {
                asm volatile("cp.async.wait_group 0;\n");
            }
            __syncthreads();

            const uint32_t sKH = sb + (uint32_t)(buf * BUF_W) * 4;
            const uint32_t sKL = sKH + ARR_W * 4;
            const uint32_t sVH = sKH + 2 * ARR_W * 4;
            const uint32_t sVL = sKH + 3 * ARR_W * 4;

            float s[8][4];
            #pragma unroll
            for (int ni = 0; ni < 8; ni++) { s[ni][0]=0; s[ni][1]=0; s[ni][2]=0; s[ni][3]=0; }
            #pragma unroll
            for (int nn = 0; nn < 4; nn++) {
                uint32_t off0 = (uint32_t)((2*nn)   * 8 * ROW_W * 4) + frag_off;
                uint32_t off1 = (uint32_t)((2*nn+1) * 8 * ROW_W * 4) + frag_off;
                #pragma unroll
                for (int kp = 0; kp < 2; kp++) {
                    uint32_t k0h[4], k0l[4], k1h[4], k1l[4];
                    ldsm_x4(k0h, sKH + off0 + kp*64);
                    ldsm_x4(k0l, sKL + off0 + kp*64);
                    ldsm_x4(k1h, sKH + off1 + kp*64);
                    ldsm_x4(k1l, sKL + off1 + kp*64);
                    MMA_PAIR(s[2*nn], s[2*nn+1], qh, ql, k0h, k0l, k1h, k1l, kp);
                }
            }

            if (t >= 2 * bx) {
                #pragma unroll
                for (int ni = 0; ni < 8; ni++) {
                    int c0 = t * 64 + ni * 8 + 2 * tig;
                    if (c0     > rA) s[ni][0] = -1e30f;
                    if (c0 + 1 > rA) s[ni][1] = -1e30f;
                    if (c0     > rB) s[ni][2] = -1e30f;
                    if (c0 + 1 > rB) s[ni][3] = -1e30f;
                }
            }

            float tmA = -INFINITY, tmB = -INFINITY;
            #pragma unroll
            for (int ni = 0; ni < 8; ni++) {
                tmA = fmaxf(tmA, fmaxf(s[ni][0], s[ni][1]));
                tmB = fmaxf(tmB, fmaxf(s[ni][2], s[ni][3]));
            }
            tmA = fmaxf(tmA, __shfl_xor_sync(0xffffffffu, tmA, 1));
            tmA = fmaxf(tmA, __shfl_xor_sync(0xffffffffu, tmA, 2));
            tmB = fmaxf(tmB, __shfl_xor_sync(0xffffffffu, tmB, 1));
            tmB = fmaxf(tmB, __shfl_xor_sync(0xffffffffu, tmB, 2));

            float mnA = fmaxf(mA, tmA), mnB = fmaxf(mB, tmB);
            float sfA = __expf(mA - mnA), sfB = __expf(mB - mnB);
            float lsA = 0.f, lsB = 0.f;

            uint32_t ph[4][4], pl[4][4];
            #pragma unroll
            for (int ni = 0; ni < 8; ni++) {
                float e0 = __expf(s[ni][0] - mnA);
                float e1 = __expf(s[ni][1] - mnA);
                float e2 = __expf(s[ni][2] - mnB);
                float e3 = __expf(s[ni][3] - mnB);
                lsA += e0 + e1;  lsB += e2 + e3;
                float h0,l0,h1,l1,h2,l2,h3,l3;
                split1(e0,h0,l0); split1(e1,h1,l1); split1(e2,h2,l2); split1(e3,h3,l3);
                int kc = ni >> 1, off = (ni & 1) * 2;
                ph[kc][off]     = pack_bf2(h0, h1);
                ph[kc][off + 1] = pack_bf2(h2, h3);
                pl[kc][off]     = pack_bf2(l0, l1);
                pl[kc][off + 1] = pack_bf2(l2, l3);
            }
            lsA += __shfl_xor_sync(0xffffffffu, lsA, 1);
            lsA += __shfl_xor_sync(0xffffffffu, lsA, 2);
            lsB += __shfl_xor_sync(0xffffffffu, lsB, 1);
            lsB += __shfl_xor_sync(0xffffffffu, lsB, 2);

            mA = mnA; mB = mnB;
            lA = lA * sfA + lsA;
            lB = lB * sfB + lsB;

            #pragma unroll
            for (int nd = 0; nd < 8; nd++) {
                o[nd][0] *= sfA; o[nd][1] *= sfA;
                o[nd][2] *= sfB; o[nd][3] *= sfB;
            }

            #pragma unroll
            for (int nn = 0; nn < 4; nn++) {
                uint32_t off0 = (uint32_t)((2*nn)   * 8 * ROW_W * 4) + frag_off;
                uint32_t off1 = (uint32_t)((2*nn+1) * 8 * ROW_W * 4) + frag_off;
                #pragma unroll
                for (int kp = 0; kp < 2; kp++) {
                    uint32_t v0h[4], v0l[4], v1h[4], v1l[4];
                    ldsm_x4(v0h, sVH + off0 + kp*64);
                    ldsm_x4(v0l, sVL + off0 + kp*64);
                    ldsm_x4(v1h, sVH + off1 + kp*64);
                    ldsm_x4(v1l, sVL + off1 + kp*64);
                    MMA_PAIR(o[2*nn], o[2*nn+1], ph, pl, v0h, v0l, v1h, v1l, kp);
                }
            }
            __syncthreads();
        }
        #undef LOAD_KV
        #undef MMA_PAIR
        #undef ENSURE

        const float iA = 1.0f / lA, iB = 1.0f / lB;
        const size_t gRowA = (size_t)(b * S_ + rA);
        const size_t gRowB = (size_t)(b * S_ + rB);
        #pragma unroll
        for (int nd = 0; nd < 8; nd++) {
            float v0 = o[nd][0] * iA, v1 = o[nd][1] * iA;
            float v2 = o[nd][2] * iB, v3 = o[nd][3] * iB;
            float h0,l0,h1,l1,h2,l2,h3,l3;
            split1(v0,h0,l0); split1(v1,h1,l1); split1(v2,h2,l2); split1(v3,h3,l3);
            size_t i0 = gRowA * D_ + h * HD_ + nd * 8 + 2 * tig;
            size_t i1 = gRowB * D_ + h * HD_ + nd * 8 + 2 * tig;
            *(uint32_t*)(g_at_hi + i0) = pack_bf2(h0, h1);
            *(uint32_t*)(g_at_lo + i0) = pack_bf2(l0, l1);
            *(uint32_t*)(g_at_hi + i1) = pack_bf2(h2, h3);
            *(uint32_t*)(g_at_lo + i1) = pack_bf2(l2, l3);
        }
    }
}

// ---------------------------------------------------------------------------
// Output-projection GEMM (unchanged R12 MODE-1 path)
// ---------------------------------------------------------------------------
__global__ __launch_bounds__(256, 2)
void gemm_out(const float* __restrict__ bias, float* __restrict__ C_out,
              int M, int N, int K)
{
    extern __shared__ uint32_t gsm[];

    const __nv_bfloat16 *Ah = g_at_hi, *Al = g_at_lo, *Bh = g_wo_hi, *Bl = g_wo_lo;

    const int tid  = threadIdx.x;
    const int lane = tid & 31;
    const int warp = tid >> 5;
    const int wr = warp >> 1, wc = warp & 1;
    const int gid = lane >> 2, tig = lane & 3;

    const int bm = blockIdx.y * 128;
    const int bn = blockIdx.x * 128;

    const int lrow   = tid >> 2;
    const int lchunk = tid & 3;

    const uint32_t sb = (uint32_t)__cvta_generic_to_shared(gsm);

    #define G_LOAD(T, S) do {                                                   \
        int k0_ = (T) * 32;                                                     \
        _Pragma("unroll")                                                       \
        for (int hh = 0; hh < 2; hh++) {                                        \
            int row = lrow + hh * 64;                                           \
            uint32_t d0 = sb + (uint32_t)((S)*GSTG + row*GLDW + lchunk*4) * 4;  \
            size_t asrc = (size_t)(bm + row) * K + k0_ + lchunk*8;              \
            size_t bsrc = (size_t)(bn + row) * K + k0_ + lchunk*8;              \
            asm volatile("cp.async.cg.shared.global [%0], [%1], 16;\n"          \
                :: "r"(d0),              "l"(Ah + asrc));                       \
            asm volatile("cp.async.cg.shared.global [%0], [%1], 16;\n"          \
                :: "r"(d0 + GARR*4),     "l"(Al + asrc));                       \
            asm volatile("cp.async.cg.shared.global [%0], [%1], 16;\n"          \
                :: "r"(d0 + 2*GARR*4),   "l"(Bh + bsrc));                       \
            asm volatile("cp.async.cg.shared.global [%0], [%1], 16;\n"          \
                :: "r"(d0 + 3*GARR*4),   "l"(Bl + bsrc));                       \
        }                                                                       \
        asm volatile("cp.async.commit_group;\n");                               \
    } while (0)

    uint32_t a_off[2], b_off[4];
    #pragma unroll
    for (int mi = 0; mi < 2; mi++)
        a_off[mi] = (uint32_t)((wr*32 + mi*16 + (lane & 15)) * GLDW * 4
                               + (lane >> 4) * 16);
    #pragma unroll
    for (int np = 0; np < 4; np++)
        b_off[np] = (uint32_t)((wc*64 + np*16 + ((lane >> 4) & 1)*8 + (lane & 7))
                               * GLDW * 4 + ((lane >> 3) & 1) * 16);

    float acc[2][8][4] = {};

    const int nt = K / 32;
    G_LOAD(0, 0);

    for (int t = 0; t < nt; t++) {
        const int stg = t & 1;
        if (t + 1 < nt) {
            G_LOAD(t + 1, (t + 1) & 1);
            asm volatile("cp.async.wait_group 1;\n");
        } else {
            asm volatile("cp.async.wait_group 0;\n");
        }
        __syncthreads();

        const uint32_t sAh = sb + (uint32_t)(stg * GSTG) * 4;
        const uint32_t sAl = sAh + GARR * 4;
        const uint32_t sBh = sAh + 2 * GARR * 4;
        const uint32_t sBl = sAh + 3 * GARR * 4;

        #pragma unroll
        for (int kcb = 0; kcb < 2; kcb++) {
            uint32_t ah[2][4], al[2][4];
            ldsm_x4(ah[0], sAh + a_off[0] + kcb*32);
            ldsm_x4(ah[1], sAh + a_off[1] + kcb*32);
            ldsm_x4(al[0], sAl + a_off[0] + kcb*32);
            ldsm_x4(al[1], sAl + a_off[1] + kcb*32);
            #pragma unroll
            for (int np = 0; np < 4; np++) {
                uint32_t bhf[4], blf[4];
                ldsm_x4(bhf, sBh + b_off[np] + kcb*32);
                ldsm_x4(blf, sBl + b_off[np] + kcb*32);
                #pragma unroll
                for (int term = 0; term < 3; term++) {
                    #pragma unroll
                    for (int sub = 0; sub < 2; sub++) {
                        #pragma unroll
                        for (int mi = 0; mi < 2; mi++) {
                            int ni = np * 2 + sub;
                            if      (term == 0) mma16816(acc[mi][ni], ah[mi], bhf + sub*2);
                            else if (term == 1) mma16816(acc[mi][ni], ah[mi], blf + sub*2);
                            else                mma16816(acc[mi][ni], al[mi], bhf + sub*2);
                        }
                    }
                }
            }
        }
        __syncthreads();
    }
    #undef G_LOAD

    #pragma unroll
    for (int mi = 0; mi < 2; mi++) {
        int row = bm + wr * 32 + mi * 16 + gid;
        #pragma unroll
        for (int ni = 0; ni < 8; ni++) {
            int col = bn + wc * 64 + ni * 8 + tig * 2;
            float2 bv = *(const float2*)(bias + col);
            float2 v0 = make_float2(acc[mi][ni][0] + bv.x, acc[mi][ni][1] + bv.y);
            float2 v1 = make_float2(acc[mi][ni][2] + bv.x, acc[mi][ni][3] + bv.y);
            *(float2*)(C_out + (size_t)row * N + col)       = v0;
            *(float2*)(C_out + (size_t)(row + 8) * N + col) = v1;
        }
    }
}

// ---------------------------------------------------------------------------
extern "C" void kernel_launch(void* const* d_in, const int* in_sizes, int n_in,
                              void* d_out, int out_size)
{
    const float* x = nullptr, *w_qkv = nullptr, *w_out = nullptr, *b_out = nullptr;
    for (int i = 0; i < n_in; i++) {
        long long n = in_sizes[i];
        if      (n == (long long)B_ * S_ * D_)      x     = (const float*)d_in[i];
        else if (n == (long long)N_QKV * D_)        w_qkv = (const float*)d_in[i];
        else if (n == (long long)D_ * D_)           w_out = (const float*)d_in[i];
        else if (n == (long long)D_)                b_out = (const float*)d_in[i];
        // mask ignored: causality is static
    }
    float* out = (float*)d_out;

    cudaFuncSetAttribute(fused_qkv_attn, cudaFuncAttributeMaxDynamicSharedMemorySize,
                         FUSED_SMEM_BYTES);
    cudaFuncSetAttribute(gemm_out, cudaFuncAttributeMaxDynamicSharedMemorySize,
                         GEMM_SMEM_BYTES);

    // 0) Reset row-tile counters (each replay), split inputs
    zero_cnt<<<1, 32>>>();
    split_bf16<0><<<4096, 256>>>(x,     (M_TOT * D_) / 4);
    split_bf16<1><<<3072, 256>>>(w_qkv, (N_QKV * D_) / 4);
    split_bf16<2><<<1024, 256>>>(w_out, (D_ * D_) / 4);

    // 1) FUSED: QKV projection (producer blocks) + causal attention (consumer
    //    blocks gated on per-row-tile counters) in one launch
    fused_qkv_attn<<<N_GEMM_BLKS + N_ATTN_BLKS, 256, FUSED_SMEM_BYTES>>>();

    // 2) Output projection: out = attn @ w_out^T + b_out
    gemm_out<<<dim3(D_ / 128, M_TOT / 128), 256, GEMM_SMEM_BYTES>>>(
        b_out, out, M_TOT, D_, D_);
}

// round 14
// speedup vs baseline: 1.1334x; 1.1334x over previous
#include <cuda_runtime.h>
#include <cuda_bf16.h>
#include <stdint.h>
#include <math.h>

// Problem constants
#define B_   2
#define S_   2048
#define D_   1024
#define H_   16
#define HD_  64
#define M_TOT (B_*S_)     // 4096
#define N_QKV (3*D_)      // 3072

#define N_ATTN_BLKS 512   // 16 q-tiles x 32 bh
#define N_OUT_BLKS  256   // 32 m-tiles x 8 n-tiles

// ---------------------------------------------------------------------------
// Scratch (allocation-free rule: __device__ globals)
// ---------------------------------------------------------------------------
__device__ __nv_bfloat16 g_x_hi [(size_t)M_TOT * D_];
__device__ __nv_bfloat16 g_x_lo [(size_t)M_TOT * D_];
__device__ __nv_bfloat16 g_wq_hi[(size_t)N_QKV * D_];
__device__ __nv_bfloat16 g_wq_lo[(size_t)N_QKV * D_];
__device__ __nv_bfloat16 g_at_hi[(size_t)M_TOT * D_];
__device__ __nv_bfloat16 g_at_lo[(size_t)M_TOT * D_];
__device__ __nv_bfloat16 g_wo_hi[(size_t)D_ * D_];
__device__ __nv_bfloat16 g_wo_lo[(size_t)D_ * D_];

__device__ __nv_bfloat16 g_aq_hi [(size_t)B_*H_*S_*HD_];
__device__ __nv_bfloat16 g_aq_lo [(size_t)B_*H_*S_*HD_];
__device__ __nv_bfloat16 g_ak_hi [(size_t)B_*H_*S_*HD_];
__device__ __nv_bfloat16 g_ak_lo [(size_t)B_*H_*S_*HD_];
__device__ __nv_bfloat16 g_avt_hi[(size_t)B_*H_*HD_*S_];
__device__ __nv_bfloat16 g_avt_lo[(size_t)B_*H_*HD_*S_];

// per-(batch,q-tile) attention completion counters; target 16 (heads)
__device__ int g_qt_cnt[32];
__global__ void zero_cnt() { if (threadIdx.x < 32) g_qt_cnt[threadIdx.x] = 0; }

// ---------------------------------------------------------------------------
// helpers
// ---------------------------------------------------------------------------
__device__ __forceinline__ uint32_t pack_bf2(float lo, float hi) {
    __nv_bfloat162 t = __floats2bfloat162_rn(lo, hi);
    return *(uint32_t*)&t;
}
__device__ __forceinline__ void split1(float v, float& h, float& l) {
    __nv_bfloat16 hb = __float2bfloat16_rn(v);
    h = __bfloat162float(hb);
    l = v - h;
}
__device__ __forceinline__ void mma16816(float* c, const uint32_t* a, const uint32_t* b)
{
    asm volatile(
        "mma.sync.aligned.m16n8k16.row.col.f32.bf16.bf16.f32 "
        "{%0,%1,%2,%3}, {%4,%5,%6,%7}, {%8,%9}, {%0,%1,%2,%3};\n"
        : "+f"(c[0]), "+f"(c[1]), "+f"(c[2]), "+f"(c[3])
        : "r"(a[0]), "r"(a[1]), "r"(a[2]), "r"(a[3]), "r"(b[0]), "r"(b[1]));
}
__device__ __forceinline__ void ldsm_x4(uint32_t* r, uint32_t addr)
{
    asm volatile(
        "ldmatrix.sync.aligned.m8n8.x4.shared.b16 {%0,%1,%2,%3}, [%4];\n"
        : "=r"(r[0]), "=r"(r[1]), "=r"(r[2]), "=r"(r[3]) : "r"(addr));
}

// ---------------------------------------------------------------------------
// Elementwise split for GEMM inputs
// ---------------------------------------------------------------------------
template<int ID>
__global__ void split_bf16(const float* __restrict__ src, int n4)
{
    __nv_bfloat16* hi = (ID == 0) ? g_x_hi : (ID == 1) ? g_wq_hi : g_wo_hi;
    __nv_bfloat16* lo = (ID == 0) ? g_x_lo : (ID == 1) ? g_wq_lo : g_wo_lo;

    for (int i = blockIdx.x * blockDim.x + threadIdx.x; i < n4;
         i += gridDim.x * blockDim.x) {
        float4 v = ((const float4*)src)[i];
        float h0,l0,h1,l1,h2,l2,h3,l3;
        split1(v.x,h0,l0); split1(v.y,h1,l1); split1(v.z,h2,l2); split1(v.w,h3,l3);
        ((uint32_t*)hi)[2*i + 0] = pack_bf2(h0, h1);
        ((uint32_t*)hi)[2*i + 1] = pack_bf2(h2, h3);
        ((uint32_t*)lo)[2*i + 0] = pack_bf2(l0, l1);
        ((uint32_t*)lo)[2*i + 1] = pack_bf2(l2, l3);
    }
}

// ---------------------------------------------------------------------------
// Layout constants
// ---------------------------------------------------------------------------
#define GLDW 20
#define GARR (128 * GLDW)
#define GSTG (4 * GARR)
#define GEMM_SMEM_BYTES (2 * GSTG * 4)   // 81920

#define ROW_W   36
#define ARR_W   (64 * ROW_W)
#define BUF_W   (4 * ARR_W)
#define ATTN_SMEM_BYTES (2 * BUF_W * 4)  // 73728

// ---------------------------------------------------------------------------
// QKV projection (proven R12 kernel, MODE-0 path only): fused qkv repack.
// ---------------------------------------------------------------------------
__global__ __launch_bounds__(256, 2)
void gemm_qkv()
{
    extern __shared__ uint32_t gsm[];

    const __nv_bfloat16 *Ah = g_x_hi, *Al = g_x_lo, *Bh = g_wq_hi, *Bl = g_wq_lo;
    const int K = D_;

    const int tid  = threadIdx.x;
    const int lane = tid & 31;
    const int warp = tid >> 5;
    const int wr = warp >> 1, wc = warp & 1;
    const int gid = lane >> 2, tig = lane & 3;

    const int bm = blockIdx.y * 128;
    const int bn = blockIdx.x * 128;

    const int lrow   = tid >> 2;
    const int lchunk = tid & 3;

    const uint32_t sb = (uint32_t)__cvta_generic_to_shared(gsm);

    #define G_LOAD(T, S) do {                                                   \
        int k0_ = (T) * 32;                                                     \
        _Pragma("unroll")                                                       \
        for (int hh = 0; hh < 2; hh++) {                                        \
            int row = lrow + hh * 64;                                           \
            uint32_t d0 = sb + (uint32_t)((S)*GSTG + row*GLDW + lchunk*4) * 4;  \
            size_t asrc = (size_t)(bm + row) * K + k0_ + lchunk*8;              \
            size_t bsrc = (size_t)(bn + row) * K + k0_ + lchunk*8;              \
            asm volatile("cp.async.cg.shared.global [%0], [%1], 16;\n"          \
                :: "r"(d0),              "l"(Ah + asrc));                       \
            asm volatile("cp.async.cg.shared.global [%0], [%1], 16;\n"          \
                :: "r"(d0 + GARR*4),     "l"(Al + asrc));                       \
            asm volatile("cp.async.cg.shared.global [%0], [%1], 16;\n"          \
                :: "r"(d0 + 2*GARR*4),   "l"(Bh + bsrc));                       \
            asm volatile("cp.async.cg.shared.global [%0], [%1], 16;\n"          \
                :: "r"(d0 + 3*GARR*4),   "l"(Bl + bsrc));                       \
        }                                                                       \
        asm volatile("cp.async.commit_group;\n");                               \
    } while (0)

    uint32_t a_off[2], b_off[4];
    #pragma unroll
    for (int mi = 0; mi < 2; mi++)
        a_off[mi] = (uint32_t)((wr*32 + mi*16 + (lane & 15)) * GLDW * 4
                               + (lane >> 4) * 16);
    #pragma unroll
    for (int np = 0; np < 4; np++)
        b_off[np] = (uint32_t)((wc*64 + np*16 + ((lane >> 4) & 1)*8 + (lane & 7))
                               * GLDW * 4 + ((lane >> 3) & 1) * 16);

    float acc[2][8][4] = {};

    const int nt = K / 32;
    G_LOAD(0, 0);

    for (int t = 0; t < nt; t++) {
        const int stg = t & 1;
        if (t + 1 < nt) {
            G_LOAD(t + 1, (t + 1) & 1);
            asm volatile("cp.async.wait_group 1;\n");
        } else {
            asm volatile("cp.async.wait_group 0;\n");
        }
        __syncthreads();

        const uint32_t sAh = sb + (uint32_t)(stg * GSTG) * 4;
        const uint32_t sAl = sAh + GARR * 4;
        const uint32_t sBh = sAh + 2 * GARR * 4;
        const uint32_t sBl = sAh + 3 * GARR * 4;

        #pragma unroll
        for (int kcb = 0; kcb < 2; kcb++) {
            uint32_t ah[2][4], al[2][4];
            ldsm_x4(ah[0], sAh + a_off[0] + kcb*32);
            ldsm_x4(ah[1], sAh + a_off[1] + kcb*32);
            ldsm_x4(al[0], sAl + a_off[0] + kcb*32);
            ldsm_x4(al[1], sAl + a_off[1] + kcb*32);
            #pragma unroll
            for (int np = 0; np < 4; np++) {
                uint32_t bhf[4], blf[4];
                ldsm_x4(bhf, sBh + b_off[np] + kcb*32);
                ldsm_x4(blf, sBl + b_off[np] + kcb*32);
                #pragma unroll
                for (int term = 0; term < 3; term++) {
                    #pragma unroll
                    for (int sub = 0; sub < 2; sub++) {
                        #pragma unroll
                        for (int mi = 0; mi < 2; mi++) {
                            int ni = np * 2 + sub;
                            if      (term == 0) mma16816(acc[mi][ni], ah[mi], bhf + sub*2);
                            else if (term == 1) mma16816(acc[mi][ni], ah[mi], blf + sub*2);
                            else                mma16816(acc[mi][ni], al[mi], bhf + sub*2);
                        }
                    }
                }
            }
        }
        __syncthreads();
    }
    #undef G_LOAD

    // Fused qkv-repack epilogue
    #pragma unroll
    for (int mi = 0; mi < 2; mi++) {
        const int row  = bm + wr * 32 + mi * 16 + gid;
        const int bidx = row >> 11;
        const int tokA = row & 2047;
        const int tokB = tokA + 8;
        #pragma unroll
        for (int ni = 0; ni < 8; ni++) {
            int col = bn + wc * 64 + ni * 8 + tig * 2;
            int h   = col / 192;
            int r   = col - h * 192;
            int bh  = bidx * H_ + h;
            float v0 = acc[mi][ni][0], v1 = acc[mi][ni][1];
            float v2 = acc[mi][ni][2], v3 = acc[mi][ni][3];
            float h0,l0,h1,l1,h2,l2,h3,l3;
            if (r < 128) {
                __nv_bfloat16 *dh, *dl;
                int d;
                if (r < 64) {
                    d = r;
                    v0 *= (1.0f/HD_); v1 *= (1.0f/HD_);
                    v2 *= (1.0f/HD_); v3 *= (1.0f/HD_);
                    dh = g_aq_hi; dl = g_aq_lo;
                } else {
                    d = r - 64;
                    dh = g_ak_hi; dl = g_ak_lo;
                }
                split1(v0,h0,l0); split1(v1,h1,l1);
                split1(v2,h2,l2); split1(v3,h3,l3);
                size_t i0 = ((size_t)bh * S_ + tokA) * HD_ + d;
                size_t i1 = ((size_t)bh * S_ + tokB) * HD_ + d;
                *(uint32_t*)(dh + i0) = pack_bf2(h0, h1);
                *(uint32_t*)(dl + i0) = pack_bf2(l0, l1);
                *(uint32_t*)(dh + i1) = pack_bf2(h2, h3);
                *(uint32_t*)(dl + i1) = pack_bf2(l2, l3);
            } else {
                int d = r - 128;
                split1(v0,h0,l0); split1(v1,h1,l1);
                split1(v2,h2,l2); split1(v3,h3,l3);
                size_t r0 = ((size_t)bh * HD_ + d)     * S_;
                size_t r1 = ((size_t)bh * HD_ + d + 1) * S_;
                g_avt_hi[r0 + tokA] = __float2bfloat16_rn(h0);
                g_avt_hi[r1 + tokA] = __float2bfloat16_rn(h1);
                g_avt_hi[r0 + tokB] = __float2bfloat16_rn(h2);
                g_avt_hi[r1 + tokB] = __float2bfloat16_rn(h3);
                g_avt_lo[r0 + tokA] = __float2bfloat16_rn(l0);
                g_avt_lo[r1 + tokA] = __float2bfloat16_rn(l1);
                g_avt_lo[r0 + tokB] = __float2bfloat16_rn(l2);
                g_avt_lo[r1 + tokB] = __float2bfloat16_rn(l3);
            }
        }
    }
}

// ---------------------------------------------------------------------------
// FUSED attention + out-projection.
// Blocks [0,512): causal attention, LPT (descending bx) — identical to R12.
//   Releases g_qt_cnt[b*16+bx] after writing its 16 head-columns of g_at.
// Blocks [512,768): out-proj tiles, ordered descending bx so dependency
//   readiness matches the attention LPT order; each waits cnt == 16.
// Wave 1 (<=296 blocks) is all-attention -> deadlock-free.
// ---------------------------------------------------------------------------
__global__ void fused_attn_out(const float* __restrict__ bias,
                               float* __restrict__ C_out)
{
    extern __shared__ uint32_t smw[];
    const int bid = blockIdx.x;
    const int tid = threadIdx.x;
    const uint32_t sb = (uint32_t)__cvta_generic_to_shared(smw);

    if (bid < N_ATTN_BLKS) {
        // ===================== attention (R12) =====================
        const int w    = tid >> 5, lane = tid & 31;
        const int gid  = lane >> 2, tig = lane & 3;
        const int bx   = 15 - (bid >> 5);          // LPT: heavy first
        const int bh   = bid & 31;
        const int b    = bh >> 4;
        const int h    = bh & 15;
        const int rA   = bx * 128 + w * 16 + gid;
        const int rB   = rA + 8;

        const uint32_t* qh_p = (const uint32_t*)(g_aq_hi + ((size_t)bh * S_ + bx*128 + w*16) * HD_);
        const uint32_t* ql_p = (const uint32_t*)(g_aq_lo + ((size_t)bh * S_ + bx*128 + w*16) * HD_);
        uint32_t qh[4][4], ql[4][4];
        #pragma unroll
        for (int kc = 0; kc < 4; kc++) {
            int w0 = 8*kc + tig;
            qh[kc][0] = qh_p[ gid      * 32 + w0    ];
            qh[kc][1] = qh_p[(gid + 8) * 32 + w0    ];
            qh[kc][2] = qh_p[ gid      * 32 + w0 + 4];
            qh[kc][3] = qh_p[(gid + 8) * 32 + w0 + 4];
            ql[kc][0] = ql_p[ gid      * 32 + w0    ];
            ql[kc][1] = ql_p[(gid + 8) * 32 + w0    ];
            ql[kc][2] = ql_p[ gid      * 32 + w0 + 4];
            ql[kc][3] = ql_p[(gid + 8) * 32 + w0 + 4];
        }

        float o[8][4] = {};
        float mA = -INFINITY, mB = -INFINITY, lA = 0.f, lB = 0.f;

        const __nv_bfloat16* kh_p = g_ak_hi  + (size_t)bh * S_ * HD_;
        const __nv_bfloat16* kl_p = g_ak_lo  + (size_t)bh * S_ * HD_;
        const __nv_bfloat16* vh_p = g_avt_hi + (size_t)bh * HD_ * S_;
        const __nv_bfloat16* vl_p = g_avt_lo + (size_t)bh * HD_ * S_;

        const int lr  = tid >> 3;
        const int seg = tid & 7;
        const uint32_t frag_off = (uint32_t)((lane & 7) * ROW_W * 4 + (lane >> 3) * 16);

        #define LOAD_KV(T, BUF) do {                                                \
            _Pragma("unroll")                                                       \
            for (int i = 0; i < 8; i++) {                                           \
                int arr = i >> 1;                                                   \
                int r   = (i & 1) * 32 + lr;                                        \
                uint32_t dst = sb + ((BUF)*BUF_W + arr*ARR_W + r*ROW_W + seg*4)*4;  \
                const __nv_bfloat16* srcp;                                          \
                if      (arr == 0) srcp = kh_p + (size_t)((T)*64 + r) * HD_ + seg*8;\
                else if (arr == 1) srcp = kl_p + (size_t)((T)*64 + r) * HD_ + seg*8;\
                else if (arr == 2) srcp = vh_p + (size_t)r * S_ + (T)*64 + seg*8;   \
                else               srcp = vl_p + (size_t)r * S_ + (T)*64 + seg*8;   \
                asm volatile("cp.async.cg.shared.global [%0], [%1], 16;\n"          \
                    :: "r"(dst), "l"(srcp));                                        \
            }                                                                       \
            asm volatile("cp.async.commit_group;\n");                               \
        } while (0)

        #define MMA_PAIR(ACC0, ACC1, AH, AL, F0H, F0L, F1H, F1L, KP) do {           \
            mma16816(ACC0, AH[2*(KP)],   F0H);     mma16816(ACC1, AH[2*(KP)],   F1H);     \
            mma16816(ACC0, AH[2*(KP)],   F0L);     mma16816(ACC1, AH[2*(KP)],   F1L);     \
            mma16816(ACC0, AL[2*(KP)],   F0H);     mma16816(ACC1, AL[2*(KP)],   F1H);     \
            mma16816(ACC0, AH[2*(KP)+1], F0H + 2); mma16816(ACC1, AH[2*(KP)+1], F1H + 2); \
            mma16816(ACC0, AH[2*(KP)+1], F0L + 2); mma16816(ACC1, AH[2*(KP)+1], F1L + 2); \
            mma16816(ACC0, AL[2*(KP)+1], F0H + 2); mma16816(ACC1, AL[2*(KP)+1], F1H + 2); \
        } while (0)

        const int nt = 2 * (bx + 1);
        LOAD_KV(0, 0);

        for (int t = 0; t < nt; t++) {
            const int buf = t & 1;
            if (t + 1 < nt) {
                LOAD_KV(t + 1, (t + 1) & 1);
                asm volatile("cp.async.wait_group 1;\n");
            } else {
                asm volatile("cp.async.wait_group 0;\n");
            }
            __syncthreads();

            const uint32_t sKH = sb + (uint32_t)(buf * BUF_W) * 4;
            const uint32_t sKL = sKH + ARR_W * 4;
            const uint32_t sVH = sKH + 2 * ARR_W * 4;
            const uint32_t sVL = sKH + 3 * ARR_W * 4;

            float s[8][4];
            #pragma unroll
            for (int ni = 0; ni < 8; ni++) { s[ni][0]=0; s[ni][1]=0; s[ni][2]=0; s[ni][3]=0; }
            #pragma unroll
            for (int nn = 0; nn < 4; nn++) {
                uint32_t off0 = (uint32_t)((2*nn)   * 8 * ROW_W * 4) + frag_off;
                uint32_t off1 = (uint32_t)((2*nn+1) * 8 * ROW_W * 4) + frag_off;
                #pragma unroll
                for (int kp = 0; kp < 2; kp++) {
                    uint32_t k0h[4], k0l[4], k1h[4], k1l[4];
                    ldsm_x4(k0h, sKH + off0 + kp*64);
                    ldsm_x4(k0l, sKL + off0 + kp*64);
                    ldsm_x4(k1h, sKH + off1 + kp*64);
                    ldsm_x4(k1l, sKL + off1 + kp*64);
                    MMA_PAIR(s[2*nn], s[2*nn+1], qh, ql, k0h, k0l, k1h, k1l, kp);
                }
            }

            if (t >= 2 * bx) {
                #pragma unroll
                for (int ni = 0; ni < 8; ni++) {
                    int c0 = t * 64 + ni * 8 + 2 * tig;
                    if (c0     > rA) s[ni][0] = -1e30f;
                    if (c0 + 1 > rA) s[ni][1] = -1e30f;
                    if (c0     > rB) s[ni][2] = -1e30f;
                    if (c0 + 1 > rB) s[ni][3] = -1e30f;
                }
            }

            float tmA = -INFINITY, tmB = -INFINITY;
            #pragma unroll
            for (int ni = 0; ni < 8; ni++) {
                tmA = fmaxf(tmA, fmaxf(s[ni][0], s[ni][1]));
                tmB = fmaxf(tmB, fmaxf(s[ni][2], s[ni][3]));
            }
            tmA = fmaxf(tmA, __shfl_xor_sync(0xffffffffu, tmA, 1));
            tmA = fmaxf(tmA, __shfl_xor_sync(0xffffffffu, tmA, 2));
            tmB = fmaxf(tmB, __shfl_xor_sync(0xffffffffu, tmB, 1));
            tmB = fmaxf(tmB, __shfl_xor_sync(0xffffffffu, tmB, 2));

            float mnA = fmaxf(mA, tmA), mnB = fmaxf(mB, tmB);
            float sfA = __expf(mA - mnA), sfB = __expf(mB - mnB);
            float lsA = 0.f, lsB = 0.f;

            uint32_t ph[4][4], pl[4][4];
            #pragma unroll
            for (int ni = 0; ni < 8; ni++) {
                float e0 = __expf(s[ni][0] - mnA);
                float e1 = __expf(s[ni][1] - mnA);
                float e2 = __expf(s[ni][2] - mnB);
                float e3 = __expf(s[ni][3] - mnB);
                lsA += e0 + e1;  lsB += e2 + e3;
                float h0,l0,h1,l1,h2,l2,h3,l3;
                split1(e0,h0,l0); split1(e1,h1,l1); split1(e2,h2,l2); split1(e3,h3,l3);
                int kc = ni >> 1, off = (ni & 1) * 2;
                ph[kc][off]     = pack_bf2(h0, h1);
                ph[kc][off + 1] = pack_bf2(h2, h3);
                pl[kc][off]     = pack_bf2(l0, l1);
                pl[kc][off + 1] = pack_bf2(l2, l3);
            }
            lsA += __shfl_xor_sync(0xffffffffu, lsA, 1);
            lsA += __shfl_xor_sync(0xffffffffu, lsA, 2);
            lsB += __shfl_xor_sync(0xffffffffu, lsB, 1);
            lsB += __shfl_xor_sync(0xffffffffu, lsB, 2);

            mA = mnA; mB = mnB;
            lA = lA * sfA + lsA;
            lB = lB * sfB + lsB;

            #pragma unroll
            for (int nd = 0; nd < 8; nd++) {
                o[nd][0] *= sfA; o[nd][1] *= sfA;
                o[nd][2] *= sfB; o[nd][3] *= sfB;
            }

            #pragma unroll
            for (int nn = 0; nn < 4; nn++) {
                uint32_t off0 = (uint32_t)((2*nn)   * 8 * ROW_W * 4) + frag_off;
                uint32_t off1 = (uint32_t)((2*nn+1) * 8 * ROW_W * 4) + frag_off;
                #pragma unroll
                for (int kp = 0; kp < 2; kp++) {
                    uint32_t v0h[4], v0l[4], v1h[4], v1l[4];
                    ldsm_x4(v0h, sVH + off0 + kp*64);
                    ldsm_x4(v0l, sVL + off0 + kp*64);
                    ldsm_x4(v1h, sVH + off1 + kp*64);
                    ldsm_x4(v1l, sVL + off1 + kp*64);
                    MMA_PAIR(o[2*nn], o[2*nn+1], ph, pl, v0h, v0l, v1h, v1l, kp);
                }
            }
            __syncthreads();
        }
        #undef LOAD_KV
        #undef MMA_PAIR

        const float iA = 1.0f / lA, iB = 1.0f / lB;
        const size_t gRowA = (size_t)(b * S_ + rA);
        const size_t gRowB = (size_t)(b * S_ + rB);
        #pragma unroll
        for (int nd = 0; nd < 8; nd++) {
            float v0 = o[nd][0] * iA, v1 = o[nd][1] * iA;
            float v2 = o[nd][2] * iB, v3 = o[nd][3] * iB;
            float h0,l0,h1,l1,h2,l2,h3,l3;
            split1(v0,h0,l0); split1(v1,h1,l1); split1(v2,h2,l2); split1(v3,h3,l3);
            size_t i0 = gRowA * D_ + h * HD_ + nd * 8 + 2 * tig;
            size_t i1 = gRowB * D_ + h * HD_ + nd * 8 + 2 * tig;
            *(uint32_t*)(g_at_hi + i0) = pack_bf2(h0, h1);
            *(uint32_t*)(g_at_lo + i0) = pack_bf2(l0, l1);
            *(uint32_t*)(g_at_hi + i1) = pack_bf2(h2, h3);
            *(uint32_t*)(g_at_lo + i1) = pack_bf2(l2, l3);
        }

        // release: writes visible, then bump (b, bx) counter
        __threadfence();
        __syncthreads();
        if (tid == 0) atomicAdd(&g_qt_cnt[b * 16 + bx], 1);

    } else {
        // ===================== out-projection consumer =====================
        const int g      = bid - N_ATTN_BLKS;        // 0..255
        const int n_tile = g & 7;
        const int mseq   = g >> 3;                   // 0..31
        const int bxx    = 15 - (mseq >> 1);         // descending bx (matches LPT)
        const int bb     = mseq & 1;
        const int m_tile = bb * 16 + bxx;
        const int bm = m_tile * 128;
        const int bn = n_tile * 128;
        const int K  = D_, N = D_;

        // acquire: wait for all 16 heads of (bb, bxx)
        if (tid == 0) {
            while (((volatile int*)g_qt_cnt)[m_tile] < 16) __nanosleep(256);
        }
        __syncthreads();
        __threadfence();

        const __nv_bfloat16 *Ah = g_at_hi, *Al = g_at_lo, *Bh = g_wo_hi, *Bl = g_wo_lo;

        const int lane = tid & 31;
        const int warp = tid >> 5;
        const int wr = warp >> 1, wc = warp & 1;
        const int gid = lane >> 2, tig = lane & 3;
        const int lrow   = tid >> 2;
        const int lchunk = tid & 3;

        #define G_LOAD(T, S) do {                                                   \
            int k0_ = (T) * 32;                                                     \
            _Pragma("unroll")                                                       \
            for (int hh = 0; hh < 2; hh++) {                                        \
                int row = lrow + hh * 64;                                           \
                uint32_t d0 = sb + (uint32_t)((S)*GSTG + row*GLDW + lchunk*4) * 4;  \
                size_t asrc = (size_t)(bm + row) * K + k0_ + lchunk*8;              \
                size_t bsrc = (size_t)(bn + row) * K + k0_ + lchunk*8;              \
                asm volatile("cp.async.cg.shared.global [%0], [%1], 16;\n"          \
                    :: "r"(d0),              "l"(Ah + asrc));                       \
                asm volatile("cp.async.cg.shared.global [%0], [%1], 16;\n"          \
                    :: "r"(d0 + GARR*4),     "l"(Al + asrc));                       \
                asm volatile("cp.async.cg.shared.global [%0], [%1], 16;\n"          \
                    :: "r"(d0 + 2*GARR*4),   "l"(Bh + bsrc));                       \
                asm volatile("cp.async.cg.shared.global [%0], [%1], 16;\n"          \
                    :: "r"(d0 + 3*GARR*4),   "l"(Bl + bsrc));                       \
            }                                                                       \
            asm volatile("cp.async.commit_group;\n");                               \
        } while (0)

        uint32_t a_off[2], b_off[4];
        #pragma unroll
        for (int mi = 0; mi < 2; mi++)
            a_off[mi] = (uint32_t)((wr*32 + mi*16 + (lane & 15)) * GLDW * 4
                                   + (lane >> 4) * 16);
        #pragma unroll
        for (int np = 0; np < 4; np++)
            b_off[np] = (uint32_t)((wc*64 + np*16 + ((lane >> 4) & 1)*8 + (lane & 7))
                                   * GLDW * 4 + ((lane >> 3) & 1) * 16);

        float acc[2][8][4] = {};

        const int nt = K / 32;
        G_LOAD(0, 0);

        for (int t = 0; t < nt; t++) {
            const int stg = t & 1;
            if (t + 1 < nt) {
                G_LOAD(t + 1, (t + 1) & 1);
                asm volatile("cp.async.wait_group 1;\n");
            } else {
                asm volatile("cp.async.wait_group 0;\n");
            }
            __syncthreads();

            const uint32_t sAh = sb + (uint32_t)(stg * GSTG) * 4;
            const uint32_t sAl = sAh + GARR * 4;
            const uint32_t sBh = sAh + 2 * GARR * 4;
            const uint32_t sBl = sAh + 3 * GARR * 4;

            #pragma unroll
            for (int kcb = 0; kcb < 2; kcb++) {
                uint32_t ah[2][4], al[2][4];
                ldsm_x4(ah[0], sAh + a_off[0] + kcb*32);
                ldsm_x4(ah[1], sAh + a_off[1] + kcb*32);
                ldsm_x4(al[0], sAl + a_off[0] + kcb*32);
                ldsm_x4(al[1], sAl + a_off[1] + kcb*32);
                #pragma unroll
                for (int np = 0; np < 4; np++) {
                    uint32_t bhf[4], blf[4];
                    ldsm_x4(bhf, sBh + b_off[np] + kcb*32);
                    ldsm_x4(blf, sBl + b_off[np] + kcb*32);
                    #pragma unroll
                    for (int term = 0; term < 3; term++) {
                        #pragma unroll
                        for (int sub = 0; sub < 2; sub++) {
                            #pragma unroll
                            for (int mi = 0; mi < 2; mi++) {
                                int ni = np * 2 + sub;
                                if      (term == 0) mma16816(acc[mi][ni], ah[mi], bhf + sub*2);
                                else if (term == 1) mma16816(acc[mi][ni], ah[mi], blf + sub*2);
                                else                mma16816(acc[mi][ni], al[mi], bhf + sub*2);
                            }
                        }
                    }
                }
            }
            __syncthreads();
        }
        #undef G_LOAD

        #pragma unroll
        for (int mi = 0; mi < 2; mi++) {
            int row = bm + wr * 32 + mi * 16 + gid;
            #pragma unroll
            for (int ni = 0; ni < 8; ni++) {
                int col = bn + wc * 64 + ni * 8 + tig * 2;
                float2 bv = *(const float2*)(bias + col);
                float2 v0 = make_float2(acc[mi][ni][0] + bv.x, acc[mi][ni][1] + bv.y);
                float2 v1 = make_float2(acc[mi][ni][2] + bv.x, acc[mi][ni][3] + bv.y);
                *(float2*)(C_out + (size_t)row * N + col)       = v0;
                *(float2*)(C_out + (size_t)(row + 8) * N + col) = v1;
            }
        }
    }
}

// ---------------------------------------------------------------------------
extern "C" void kernel_launch(void* const* d_in, const int* in_sizes, int n_in,
                              void* d_out, int out_size)
{
    const float* x = nullptr, *w_qkv = nullptr, *w_out = nullptr, *b_out = nullptr;
    for (int i = 0; i < n_in; i++) {
        long long n = in_sizes[i];
        if      (n == (long long)B_ * S_ * D_)      x     = (const float*)d_in[i];
        else if (n == (long long)N_QKV * D_)        w_qkv = (const float*)d_in[i];
        else if (n == (long long)D_ * D_)           w_out = (const float*)d_in[i];
        else if (n == (long long)D_)                b_out = (const float*)d_in[i];
        // mask ignored: causality is static
    }
    float* out = (float*)d_out;

    cudaFuncSetAttribute(gemm_qkv, cudaFuncAttributeMaxDynamicSharedMemorySize,
                         GEMM_SMEM_BYTES);
    cudaFuncSetAttribute(fused_attn_out, cudaFuncAttributeMaxDynamicSharedMemorySize,
                         GEMM_SMEM_BYTES);

    // 0) Reset counters; split inputs into bf16 hi/lo
    zero_cnt<<<1, 32>>>();
    split_bf16<0><<<4096, 256>>>(x,     (M_TOT * D_) / 4);
    split_bf16<1><<<3072, 256>>>(w_qkv, (N_QKV * D_) / 4);
    split_bf16<2><<<1024, 256>>>(w_out, (D_ * D_) / 4);

    // 1) QKV projection + fused repack
    gemm_qkv<<<dim3(N_QKV / 128, M_TOT / 128), 256, GEMM_SMEM_BYTES>>>();

    // 2) FUSED: causal attention (LPT) + out-projection (counter-gated,
    //    descending-bx so deps match the LPT completion order)
    fused_attn_out<<<N_ATTN_BLKS + N_OUT_BLKS, 256, GEMM_SMEM_BYTES>>>(b_out, out);
}

// round 15
// speedup vs baseline: 1.1705x; 1.0327x over previous
#include <cuda_runtime.h>
#include <cuda_bf16.h>
#include <stdint.h>
#include <math.h>

// Problem constants
#define B_   2
#define S_   2048
#define D_   1024
#define H_   16
#define HD_  64
#define M_TOT (B_*S_)     // 4096
#define N_QKV (3*D_)      // 3072

// ---------------------------------------------------------------------------
// Scratch (allocation-free rule: __device__ globals)
// ---------------------------------------------------------------------------
__device__ __nv_bfloat16 g_x_hi [(size_t)M_TOT * D_];
__device__ __nv_bfloat16 g_x_lo [(size_t)M_TOT * D_];
__device__ __nv_bfloat16 g_wq_hi[(size_t)N_QKV * D_];
__device__ __nv_bfloat16 g_wq_lo[(size_t)N_QKV * D_];
__device__ __nv_bfloat16 g_at_hi[(size_t)M_TOT * D_];   // attention out (split)
__device__ __nv_bfloat16 g_at_lo[(size_t)M_TOT * D_];
__device__ __nv_bfloat16 g_wo_hi[(size_t)D_ * D_];
__device__ __nv_bfloat16 g_wo_lo[(size_t)D_ * D_];

// Head-contiguous attention operands (split), written by gemm0 epilogue
__device__ __nv_bfloat16 g_aq_hi [(size_t)B_*H_*S_*HD_];  // [bh][S][64], q/64
__device__ __nv_bfloat16 g_aq_lo [(size_t)B_*H_*S_*HD_];
__device__ __nv_bfloat16 g_ak_hi [(size_t)B_*H_*S_*HD_];  // [bh][S][64]
__device__ __nv_bfloat16 g_ak_lo [(size_t)B_*H_*S_*HD_];
__device__ __nv_bfloat16 g_avt_hi[(size_t)B_*H_*HD_*S_];  // [bh][64][S]  (V^T)
__device__ __nv_bfloat16 g_avt_lo[(size_t)B_*H_*HD_*S_];

// ---------------------------------------------------------------------------
// helpers
// ---------------------------------------------------------------------------
__device__ __forceinline__ uint32_t pack_bf2(float lo, float hi) {
    __nv_bfloat162 t = __floats2bfloat162_rn(lo, hi);   // .x = lo half
    return *(uint32_t*)&t;
}
__device__ __forceinline__ void split1(float v, float& h, float& l) {
    __nv_bfloat16 hb = __float2bfloat16_rn(v);
    h = __bfloat162float(hb);
    l = v - h;
}
__device__ __forceinline__ void mma16816(float* c, const uint32_t* a, const uint32_t* b)
{
    asm volatile(
        "mma.sync.aligned.m16n8k16.row.col.f32.bf16.bf16.f32 "
        "{%0,%1,%2,%3}, {%4,%5,%6,%7}, {%8,%9}, {%0,%1,%2,%3};\n"
        : "+f"(c[0]), "+f"(c[1]), "+f"(c[2]), "+f"(c[3])
        : "r"(a[0]), "r"(a[1]), "r"(a[2]), "r"(a[3]), "r"(b[0]), "r"(b[1]));
}
__device__ __forceinline__ void ldsm_x4(uint32_t* r, uint32_t addr)
{
    asm volatile(
        "ldmatrix.sync.aligned.m8n8.x4.shared.b16 {%0,%1,%2,%3}, [%4];\n"
        : "=r"(r[0]), "=r"(r[1]), "=r"(r[2]), "=r"(r[3]) : "r"(addr));
}

// ---------------------------------------------------------------------------
// Merged elementwise split: one launch handles x | w_qkv | w_out.
// Index space is in float4 units: [0, XN4) -> x, [XN4, XN4+WQ4) -> w_qkv,
// [XN4+WQ4, XN4+WQ4+WO4) -> w_out.
// ---------------------------------------------------------------------------
#define XN4 ((M_TOT * D_) / 4)
#define WQ4 ((N_QKV * D_) / 4)
#define WO4 ((D_ * D_) / 4)
#define TOT4 (XN4 + WQ4 + WO4)

__global__ void split_all(const float* __restrict__ x,
                          const float* __restrict__ w_qkv,
                          const float* __restrict__ w_out)
{
    for (int i = blockIdx.x * blockDim.x + threadIdx.x; i < TOT4;
         i += gridDim.x * blockDim.x) {
        const float* src;
        __nv_bfloat16 *hi, *lo;
        int j = i;
        if (j < XN4)            { src = x;     hi = g_x_hi;  lo = g_x_lo;  }
        else if ((j -= XN4) < WQ4) { src = w_qkv; hi = g_wq_hi; lo = g_wq_lo; }
        else { j -= WQ4;          src = w_out; hi = g_wo_hi; lo = g_wo_lo; }

        float4 v = ((const float4*)src)[j];
        float h0,l0,h1,l1,h2,l2,h3,l3;
        split1(v.x,h0,l0); split1(v.y,h1,l1); split1(v.z,h2,l2); split1(v.w,h3,l3);
        ((uint32_t*)hi)[2*j + 0] = pack_bf2(h0, h1);
        ((uint32_t*)hi)[2*j + 1] = pack_bf2(h2, h3);
        ((uint32_t*)lo)[2*j + 0] = pack_bf2(l0, l1);
        ((uint32_t*)lo)[2*j + 1] = pack_bf2(l2, l3);
    }
}

// ---------------------------------------------------------------------------
// bf16x3-split tensor-core NT GEMM (R12 config: 128x128 tile, 2 CTA/SM).
// MODE 0: epilogue fuses the qkv repack. MODE 1: C = d_out + bias.
// ---------------------------------------------------------------------------
#define GLDW 20
#define GARR (128 * GLDW)
#define GSTG (4 * GARR)
#define GEMM_SMEM_BYTES (2 * GSTG * 4)   // 81920

template<int MODE>
__global__ __launch_bounds__(256, 2)
void gemm_bf16x3(const float* __restrict__ bias, float* __restrict__ C_out,
                 int M, int N, int K)
{
    extern __shared__ uint32_t gsm[];

    const __nv_bfloat16 *Ah, *Al, *Bh, *Bl;
    if (MODE == 0) { Ah = g_x_hi;  Al = g_x_lo;  Bh = g_wq_hi; Bl = g_wq_lo; }
    else           { Ah = g_at_hi; Al = g_at_lo; Bh = g_wo_hi; Bl = g_wo_lo; }

    const int tid  = threadIdx.x;
    const int lane = tid & 31;
    const int warp = tid >> 5;
    const int wr = warp >> 1, wc = warp & 1;
    const int gid = lane >> 2, tig = lane & 3;

    const int bm = blockIdx.y * 128;
    const int bn = blockIdx.x * 128;

    const int lrow   = tid >> 2;
    const int lchunk = tid & 3;

    const uint32_t sb = (uint32_t)__cvta_generic_to_shared(gsm);

    #define G_LOAD(T, S) do {                                                   \
        int k0_ = (T) * 32;                                                     \
        _Pragma("unroll")                                                       \
        for (int hh = 0; hh < 2; hh++) {                                        \
            int row = lrow + hh * 64;                                           \
            uint32_t d0 = sb + (uint32_t)((S)*GSTG + row*GLDW + lchunk*4) * 4;  \
            size_t asrc = (size_t)(bm + row) * K + k0_ + lchunk*8;              \
            size_t bsrc = (size_t)(bn + row) * K + k0_ + lchunk*8;              \
            asm volatile("cp.async.cg.shared.global [%0], [%1], 16;\n"          \
                :: "r"(d0),              "l"(Ah + asrc));                       \
            asm volatile("cp.async.cg.shared.global [%0], [%1], 16;\n"          \
                :: "r"(d0 + GARR*4),     "l"(Al + asrc));                       \
            asm volatile("cp.async.cg.shared.global [%0], [%1], 16;\n"          \
                :: "r"(d0 + 2*GARR*4),   "l"(Bh + bsrc));                       \
            asm volatile("cp.async.cg.shared.global [%0], [%1], 16;\n"          \
                :: "r"(d0 + 3*GARR*4),   "l"(Bl + bsrc));                       \
        }                                                                       \
        asm volatile("cp.async.commit_group;\n");                               \
    } while (0)

    uint32_t a_off[2], b_off[4];
    #pragma unroll
    for (int mi = 0; mi < 2; mi++)
        a_off[mi] = (uint32_t)((wr*32 + mi*16 + (lane & 15)) * GLDW * 4
                               + (lane >> 4) * 16);
    #pragma unroll
    for (int np = 0; np < 4; np++)
        b_off[np] = (uint32_t)((wc*64 + np*16 + ((lane >> 4) & 1)*8 + (lane & 7))
                               * GLDW * 4 + ((lane >> 3) & 1) * 16);

    float acc[2][8][4] = {};

    const int nt = K / 32;
    G_LOAD(0, 0);

    for (int t = 0; t < nt; t++) {
        const int stg = t & 1;
        if (t + 1 < nt) {
            G_LOAD(t + 1, (t + 1) & 1);
            asm volatile("cp.async.wait_group 1;\n");
        } else {
            asm volatile("cp.async.wait_group 0;\n");
        }
        __syncthreads();

        const uint32_t sAh = sb + (uint32_t)(stg * GSTG) * 4;
        const uint32_t sAl = sAh + GARR * 4;
        const uint32_t sBh = sAh + 2 * GARR * 4;
        const uint32_t sBl = sAh + 3 * GARR * 4;

        #pragma unroll
        for (int kcb = 0; kcb < 2; kcb++) {
            uint32_t ah[2][4], al[2][4];
            ldsm_x4(ah[0], sAh + a_off[0] + kcb*32);
            ldsm_x4(ah[1], sAh + a_off[1] + kcb*32);
            ldsm_x4(al[0], sAl + a_off[0] + kcb*32);
            ldsm_x4(al[1], sAl + a_off[1] + kcb*32);
            #pragma unroll
            for (int np = 0; np < 4; np++) {
                uint32_t bhf[4], blf[4];
                ldsm_x4(bhf, sBh + b_off[np] + kcb*32);
                ldsm_x4(blf, sBl + b_off[np] + kcb*32);
                #pragma unroll
                for (int term = 0; term < 3; term++) {
                    #pragma unroll
                    for (int sub = 0; sub < 2; sub++) {
                        #pragma unroll
                        for (int mi = 0; mi < 2; mi++) {
                            int ni = np * 2 + sub;
                            if      (term == 0) mma16816(acc[mi][ni], ah[mi], bhf + sub*2);
                            else if (term == 1) mma16816(acc[mi][ni], ah[mi], blf + sub*2);
                            else                mma16816(acc[mi][ni], al[mi], bhf + sub*2);
                        }
                    }
                }
            }
        }
        __syncthreads();
    }
    #undef G_LOAD

    // ---- Epilogue ----
    if (MODE == 1) {
        #pragma unroll
        for (int mi = 0; mi < 2; mi++) {
            int row = bm + wr * 32 + mi * 16 + gid;
            #pragma unroll
            for (int ni = 0; ni < 8; ni++) {
                int col = bn + wc * 64 + ni * 8 + tig * 2;
                float2 bv = *(const float2*)(bias + col);
                float2 v0 = make_float2(acc[mi][ni][0] + bv.x, acc[mi][ni][1] + bv.y);
                float2 v1 = make_float2(acc[mi][ni][2] + bv.x, acc[mi][ni][3] + bv.y);
                *(float2*)(C_out + (size_t)row * N + col)       = v0;
                *(float2*)(C_out + (size_t)(row + 8) * N + col) = v1;
            }
        }
    } else {
        // Fused qkv repack
        #pragma unroll
        for (int mi = 0; mi < 2; mi++) {
            const int row  = bm + wr * 32 + mi * 16 + gid;
            const int bidx = row >> 11;
            const int tokA = row & 2047;
            const int tokB = tokA + 8;
            #pragma unroll
            for (int ni = 0; ni < 8; ni++) {
                int col = bn + wc * 64 + ni * 8 + tig * 2;
                int h   = col / 192;
                int r   = col - h * 192;
                int bh  = bidx * H_ + h;
                float v0 = acc[mi][ni][0], v1 = acc[mi][ni][1];
                float v2 = acc[mi][ni][2], v3 = acc[mi][ni][3];
                float h0,l0,h1,l1,h2,l2,h3,l3;
                if (r < 128) {
                    __nv_bfloat16 *dh, *dl;
                    int d;
                    if (r < 64) {
                        d = r;
                        v0 *= (1.0f/HD_); v1 *= (1.0f/HD_);
                        v2 *= (1.0f/HD_); v3 *= (1.0f/HD_);
                        dh = g_aq_hi; dl = g_aq_lo;
                    } else {
                        d = r - 64;
                        dh = g_ak_hi; dl = g_ak_lo;
                    }
                    split1(v0,h0,l0); split1(v1,h1,l1);
                    split1(v2,h2,l2); split1(v3,h3,l3);
                    size_t i0 = ((size_t)bh * S_ + tokA) * HD_ + d;
                    size_t i1 = ((size_t)bh * S_ + tokB) * HD_ + d;
                    *(uint32_t*)(dh + i0) = pack_bf2(h0, h1);
                    *(uint32_t*)(dl + i0) = pack_bf2(l0, l1);
                    *(uint32_t*)(dh + i1) = pack_bf2(h2, h3);
                    *(uint32_t*)(dl + i1) = pack_bf2(l2, l3);
                } else {
                    int d = r - 128;
                    split1(v0,h0,l0); split1(v1,h1,l1);
                    split1(v2,h2,l2); split1(v3,h3,l3);
                    size_t r0 = ((size_t)bh * HD_ + d)     * S_;
                    size_t r1 = ((size_t)bh * HD_ + d + 1) * S_;
                    g_avt_hi[r0 + tokA] = __float2bfloat16_rn(h0);
                    g_avt_hi[r1 + tokA] = __float2bfloat16_rn(h1);
                    g_avt_hi[r0 + tokB] = __float2bfloat16_rn(h2);
                    g_avt_hi[r1 + tokB] = __float2bfloat16_rn(h3);
                    g_avt_lo[r0 + tokA] = __float2bfloat16_rn(l0);
                    g_avt_lo[r1 + tokA] = __float2bfloat16_rn(l1);
                    g_avt_lo[r0 + tokB] = __float2bfloat16_rn(l2);
                    g_avt_lo[r1 + tokB] = __float2bfloat16_rn(l3);
                }
            }
        }
    }
}

// ---------------------------------------------------------------------------
// Tensor-core causal flash attention with LPT block order (R12, unchanged).
// ---------------------------------------------------------------------------
#define ROW_W   36
#define ARR_W   (64 * ROW_W)
#define BUF_W   (4 * ARR_W)
#define ATTN_SMEM_BYTES (2 * BUF_W * 4)

__global__ __launch_bounds__(256)
void attn_mma()
{
    extern __shared__ uint32_t smw[];
    const int tid  = threadIdx.x;
    const int w    = tid >> 5, lane = tid & 31;
    const int gid  = lane >> 2, tig = lane & 3;
    const int bx   = (int)(gridDim.y - 1 - blockIdx.y);   // LPT: heavy first
    const int bh   = blockIdx.x;
    const int b    = bh >> 4;
    const int h    = bh & 15;
    const int rA   = bx * 128 + w * 16 + gid;
    const int rB   = rA + 8;

    const uint32_t* qh_p = (const uint32_t*)(g_aq_hi + ((size_t)bh * S_ + bx*128 + w*16) * HD_);
    const uint32_t* ql_p = (const uint32_t*)(g_aq_lo + ((size_t)bh * S_ + bx*128 + w*16) * HD_);
    uint32_t qh[4][4], ql[4][4];
    #pragma unroll
    for (int kc = 0; kc < 4; kc++) {
        int w0 = 8*kc + tig;
        qh[kc][0] = qh_p[ gid      * 32 + w0    ];
        qh[kc][1] = qh_p[(gid + 8) * 32 + w0    ];
        qh[kc][2] = qh_p[ gid      * 32 + w0 + 4];
        qh[kc][3] = qh_p[(gid + 8) * 32 + w0 + 4];
        ql[kc][0] = ql_p[ gid      * 32 + w0    ];
        ql[kc][1] = ql_p[(gid + 8) * 32 + w0    ];
        ql[kc][2] = ql_p[ gid      * 32 + w0 + 4];
        ql[kc][3] = ql_p[(gid + 8) * 32 + w0 + 4];
    }

    float o[8][4] = {};
    float mA = -INFINITY, mB = -INFINITY, lA = 0.f, lB = 0.f;

    const __nv_bfloat16* kh_p = g_ak_hi  + (size_t)bh * S_ * HD_;
    const __nv_bfloat16* kl_p = g_ak_lo  + (size_t)bh * S_ * HD_;
    const __nv_bfloat16* vh_p = g_avt_hi + (size_t)bh * HD_ * S_;
    const __nv_bfloat16* vl_p = g_avt_lo + (size_t)bh * HD_ * S_;

    const uint32_t sb = (uint32_t)__cvta_generic_to_shared(smw);
    const int lr  = tid >> 3;
    const int seg = tid & 7;

    const uint32_t frag_off = (uint32_t)((lane & 7) * ROW_W * 4 + (lane >> 3) * 16);

    #define LOAD_KV(T, BUF) do {                                                \
        _Pragma("unroll")                                                       \
        for (int i = 0; i < 8; i++) {                                           \
            int arr = i >> 1;                                                   \
            int r   = (i & 1) * 32 + lr;                                        \
            uint32_t dst = sb + ((BUF)*BUF_W + arr*ARR_W + r*ROW_W + seg*4)*4;  \
            const __nv_bfloat16* srcp;                                          \
            if      (arr == 0) srcp = kh_p + (size_t)((T)*64 + r) * HD_ + seg*8;\
            else if (arr == 1) srcp = kl_p + (size_t)((T)*64 + r) * HD_ + seg*8;\
            else if (arr == 2) srcp = vh_p + (size_t)r * S_ + (T)*64 + seg*8;   \
            else               srcp = vl_p + (size_t)r * S_ + (T)*64 + seg*8;   \
            asm volatile("cp.async.cg.shared.global [%0], [%1], 16;\n"          \
                :: "r"(dst), "l"(srcp));                                        \
        }                                                                       \
        asm volatile("cp.async.commit_group;\n");                               \
    } while (0)

    #define MMA_PAIR(ACC0, ACC1, AH, AL, F0H, F0L, F1H, F1L, KP) do {           \
        mma16816(ACC0, AH[2*(KP)],   F0H);     mma16816(ACC1, AH[2*(KP)],   F1H);     \
        mma16816(ACC0, AH[2*(KP)],   F0L);     mma16816(ACC1, AH[2*(KP)],   F1L);     \
        mma16816(ACC0, AL[2*(KP)],   F0H);     mma16816(ACC1, AL[2*(KP)],   F1H);     \
        mma16816(ACC0, AH[2*(KP)+1], F0H + 2); mma16816(ACC1, AH[2*(KP)+1], F1H + 2); \
        mma16816(ACC0, AH[2*(KP)+1], F0L + 2); mma16816(ACC1, AH[2*(KP)+1], F1L + 2); \
        mma16816(ACC0, AL[2*(KP)+1], F0H + 2); mma16816(ACC1, AL[2*(KP)+1], F1H + 2); \
    } while (0)

    const int nt = 2 * (bx + 1);
    LOAD_KV(0, 0);

    for (int t = 0; t < nt; t++) {
        const int buf = t & 1;
        if (t + 1 < nt) {
            LOAD_KV(t + 1, (t + 1) & 1);
            asm volatile("cp.async.wait_group 1;\n");
        } else {
            asm volatile("cp.async.wait_group 0;\n");
        }
        __syncthreads();

        const uint32_t sKH = sb + (uint32_t)(buf * BUF_W) * 4;
        const uint32_t sKL = sKH + ARR_W * 4;
        const uint32_t sVH = sKH + 2 * ARR_W * 4;
        const uint32_t sVL = sKH + 3 * ARR_W * 4;

        float s[8][4];
        #pragma unroll
        for (int ni = 0; ni < 8; ni++) { s[ni][0]=0; s[ni][1]=0; s[ni][2]=0; s[ni][3]=0; }
        #pragma unroll
        for (int nn = 0; nn < 4; nn++) {
            uint32_t off0 = (uint32_t)((2*nn)   * 8 * ROW_W * 4) + frag_off;
            uint32_t off1 = (uint32_t)((2*nn+1) * 8 * ROW_W * 4) + frag_off;
            #pragma unroll
            for (int kp = 0; kp < 2; kp++) {
                uint32_t k0h[4], k0l[4], k1h[4], k1l[4];
                ldsm_x4(k0h, sKH + off0 + kp*64);
                ldsm_x4(k0l, sKL + off0 + kp*64);
                ldsm_x4(k1h, sKH + off1 + kp*64);
                ldsm_x4(k1l, sKL + off1 + kp*64);
                MMA_PAIR(s[2*nn], s[2*nn+1], qh, ql, k0h, k0l, k1h, k1l, kp);
            }
        }

        if (t >= 2 * bx) {
            #pragma unroll
            for (int ni = 0; ni < 8; ni++) {
                int c0 = t * 64 + ni * 8 + 2 * tig;
                if (c0     > rA) s[ni][0] = -1e30f;
                if (c0 + 1 > rA) s[ni][1] = -1e30f;
                if (c0     > rB) s[ni][2] = -1e30f;
                if (c0 + 1 > rB) s[ni][3] = -1e30f;
            }
        }

        float tmA = -INFINITY, tmB = -INFINITY;
        #pragma unroll
        for (int ni = 0; ni < 8; ni++) {
            tmA = fmaxf(tmA, fmaxf(s[ni][0], s[ni][1]));
            tmB = fmaxf(tmB, fmaxf(s[ni][2], s[ni][3]));
        }
        tmA = fmaxf(tmA, __shfl_xor_sync(0xffffffffu, tmA, 1));
        tmA = fmaxf(tmA, __shfl_xor_sync(0xffffffffu, tmA, 2));
        tmB = fmaxf(tmB, __shfl_xor_sync(0xffffffffu, tmB, 1));
        tmB = fmaxf(tmB, __shfl_xor_sync(0xffffffffu, tmB, 2));

        float mnA = fmaxf(mA, tmA), mnB = fmaxf(mB, tmB);
        float sfA = __expf(mA - mnA), sfB = __expf(mB - mnB);
        float lsA = 0.f, lsB = 0.f;

        uint32_t ph[4][4], pl[4][4];
        #pragma unroll
        for (int ni = 0; ni < 8; ni++) {
            float e0 = __expf(s[ni][0] - mnA);
            float e1 = __expf(s[ni][1] - mnA);
            float e2 = __expf(s[ni][2] - mnB);
            float e3 = __expf(s[ni][3] - mnB);
            lsA += e0 + e1;  lsB += e2 + e3;
            float h0,l0,h1,l1,h2,l2,h3,l3;
            split1(e0,h0,l0); split1(e1,h1,l1); split1(e2,h2,l2); split1(e3,h3,l3);
            int kc = ni >> 1, off = (ni & 1) * 2;
            ph[kc][off]     = pack_bf2(h0, h1);
            ph[kc][off + 1] = pack_bf2(h2, h3);
            pl[kc][off]     = pack_bf2(l0, l1);
            pl[kc][off + 1] = pack_bf2(l2, l3);
        }
        lsA += __shfl_xor_sync(0xffffffffu, lsA, 1);
        lsA += __shfl_xor_sync(0xffffffffu, lsA, 2);
        lsB += __shfl_xor_sync(0xffffffffu, lsB, 1);
        lsB += __shfl_xor_sync(0xffffffffu, lsB, 2);

        mA = mnA; mB = mnB;
        lA = lA * sfA + lsA;
        lB = lB * sfB + lsB;

        #pragma unroll
        for (int nd = 0; nd < 8; nd++) {
            o[nd][0] *= sfA; o[nd][1] *= sfA;
            o[nd][2] *= sfB; o[nd][3] *= sfB;
        }

        #pragma unroll
        for (int nn = 0; nn < 4; nn++) {
            uint32_t off0 = (uint32_t)((2*nn)   * 8 * ROW_W * 4) + frag_off;
            uint32_t off1 = (uint32_t)((2*nn+1) * 8 * ROW_W * 4) + frag_off;
            #pragma unroll
            for (int kp = 0; kp < 2; kp++) {
                uint32_t v0h[4], v0l[4], v1h[4], v1l[4];
                ldsm_x4(v0h, sVH + off0 + kp*64);
                ldsm_x4(v0l, sVL + off0 + kp*64);
                ldsm_x4(v1h, sVH + off1 + kp*64);
                ldsm_x4(v1l, sVL + off1 + kp*64);
                MMA_PAIR(o[2*nn], o[2*nn+1], ph, pl, v0h, v0l, v1h, v1l, kp);
            }
        }
        __syncthreads();
    }
    #undef LOAD_KV
    #undef MMA_PAIR

    const float iA = 1.0f / lA, iB = 1.0f / lB;
    const size_t gRowA = (size_t)(b * S_ + rA);
    const size_t gRowB = (size_t)(b * S_ + rB);
    #pragma unroll
    for (int nd = 0; nd < 8; nd++) {
        float v0 = o[nd][0] * iA, v1 = o[nd][1] * iA;
        float v2 = o[nd][2] * iB, v3 = o[nd][3] * iB;
        float h0,l0,h1,l1,h2,l2,h3,l3;
        split1(v0,h0,l0); split1(v1,h1,l1); split1(v2,h2,l2); split1(v3,h3,l3);
        size_t i0 = gRowA * D_ + h * HD_ + nd * 8 + 2 * tig;
        size_t i1 = gRowB * D_ + h * HD_ + nd * 8 + 2 * tig;
        *(uint32_t*)(g_at_hi + i0) = pack_bf2(h0, h1);
        *(uint32_t*)(g_at_lo + i0) = pack_bf2(l0, l1);
        *(uint32_t*)(g_at_hi + i1) = pack_bf2(h2, h3);
        *(uint32_t*)(g_at_lo + i1) = pack_bf2(l2, l3);
    }
}

// ---------------------------------------------------------------------------
extern "C" void kernel_launch(void* const* d_in, const int* in_sizes, int n_in,
                              void* d_out, int out_size)
{
    const float* x = nullptr, *w_qkv = nullptr, *w_out = nullptr, *b_out = nullptr;
    for (int i = 0; i < n_in; i++) {
        long long n = in_sizes[i];
        if      (n == (long long)B_ * S_ * D_)      x     = (const float*)d_in[i];
        else if (n == (long long)N_QKV * D_)        w_qkv = (const float*)d_in[i];
        else if (n == (long long)D_ * D_)           w_out = (const float*)d_in[i];
        else if (n == (long long)D_)                b_out = (const float*)d_in[i];
        // mask ignored: causality is static
    }
    float* out = (float*)d_out;

    cudaFuncSetAttribute(attn_mma, cudaFuncAttributeMaxDynamicSharedMemorySize,
                         ATTN_SMEM_BYTES);
    cudaFuncSetAttribute(gemm_bf16x3<0>, cudaFuncAttributeMaxDynamicSharedMemorySize,
                         GEMM_SMEM_BYTES);
    cudaFuncSetAttribute(gemm_bf16x3<1>, cudaFuncAttributeMaxDynamicSharedMemorySize,
                         GEMM_SMEM_BYTES);

    // 0) Merged split of x, w_qkv, w_out into bf16 hi/lo (one launch)
    split_all<<<2368, 256>>>(x, w_qkv, w_out);

    // 1) QKV projection + fused repack
    gemm_bf16x3<0><<<dim3(N_QKV / 128, M_TOT / 128), 256, GEMM_SMEM_BYTES>>>(
        nullptr, nullptr, M_TOT, N_QKV, D_);

    // 2) Tensor-core causal flash attention (LPT block order) -> g_at_hi/lo
    attn_mma<<<dim3(B_ * H_, S_ / 128), 256, ATTN_SMEM_BYTES>>>();

    // 3) Output projection: out = attn @ w_out^T + b_out
    gemm_bf16x3<1><<<dim3(D_ / 128, M_TOT / 128), 256, GEMM_SMEM_BYTES>>>(
        b_out, out, M_TOT, D_, D_);
}

// round 17
// speedup vs baseline: 2.6282x; 2.2454x over previous
#include <cuda_runtime.h>
#include <cuda_fp16.h>
#include <stdint.h>
#include <math.h>

// Problem constants
#define B_   2
#define S_   2048
#define D_   1024
#define H_   16
#define HD_  64
#define M_TOT (B_*S_)     // 4096
#define N_QKV (3*D_)      // 3072

// ---------------------------------------------------------------------------
// Scratch (allocation-free rule: __device__ globals) — fp16 single precision
// ---------------------------------------------------------------------------
__device__ __half g_x  [(size_t)M_TOT * D_];
__device__ __half g_wq [(size_t)N_QKV * D_];
__device__ __half g_at [(size_t)M_TOT * D_];    // attention out
__device__ __half g_wo [(size_t)D_ * D_];

// Head-contiguous attention operands, written by gemm0 epilogue
__device__ __half g_aq [(size_t)B_*H_*S_*HD_];  // [bh][S][64], q/64
__device__ __half g_ak [(size_t)B_*H_*S_*HD_];  // [bh][S][64]
__device__ __half g_avt[(size_t)B_*H_*HD_*S_];  // [bh][64][S]  (V^T)

// ---------------------------------------------------------------------------
// helpers
// ---------------------------------------------------------------------------
__device__ __forceinline__ uint32_t pack_h2(float lo, float hi) {
    __half2 t = __floats2half2_rn(lo, hi);   // .x = lo half
    return *(uint32_t*)&t;
}
__device__ __forceinline__ void mma16816(float* c, const uint32_t* a, const uint32_t* b)
{
    asm volatile(
        "mma.sync.aligned.m16n8k16.row.col.f32.f16.f16.f32 "
        "{%0,%1,%2,%3}, {%4,%5,%6,%7}, {%8,%9}, {%0,%1,%2,%3};\n"
        : "+f"(c[0]), "+f"(c[1]), "+f"(c[2]), "+f"(c[3])
        : "r"(a[0]), "r"(a[1]), "r"(a[2]), "r"(a[3]), "r"(b[0]), "r"(b[1]));
}
__device__ __forceinline__ void ldsm_x4(uint32_t* r, uint32_t addr)
{
    asm volatile(
        "ldmatrix.sync.aligned.m8n8.x4.shared.b16 {%0,%1,%2,%3}, [%4];\n"
        : "=r"(r[0]), "=r"(r[1]), "=r"(r[2]), "=r"(r[3]) : "r"(addr));
}

// ---------------------------------------------------------------------------
// Merged elementwise fp16 convert: one launch handles x | w_qkv | w_out.
// ---------------------------------------------------------------------------
#define XN4 ((M_TOT * D_) / 4)
#define WQ4 ((N_QKV * D_) / 4)
#define WO4 ((D_ * D_) / 4)
#define TOT4 (XN4 + WQ4 + WO4)

__global__ void cvt_all(const float* __restrict__ x,
                        const float* __restrict__ w_qkv,
                        const float* __restrict__ w_out)
{
    for (int i = blockIdx.x * blockDim.x + threadIdx.x; i < TOT4;
         i += gridDim.x * blockDim.x) {
        const float* src;
        __half* dst;
        int j = i;
        if (j < XN4)               { src = x;     dst = g_x;  }
        else if ((j -= XN4) < WQ4) { src = w_qkv; dst = g_wq; }
        else { j -= WQ4;             src = w_out; dst = g_wo; }

        float4 v = ((const float4*)src)[j];
        uint2 o;
        o.x = pack_h2(v.x, v.y);
        o.y = pack_h2(v.z, v.w);
        *(uint2*)(dst + (size_t)j * 4) = o;
    }
}

// ---------------------------------------------------------------------------
// fp16 tensor-core NT GEMM (single-term): C[M,N] = A[M,K] @ B[N,K]^T (+ bias)
// 128x128 CTA tile, 8 warps (4x2), warp tile 32x64, BK=32, 2-stage cp.async.
// MODE 0: epilogue fuses the qkv repack. MODE 1: C = d_out + bias.
// Row layout: 20 uint32 words (16 data + 4 pad), conflict-free for ldmatrix.
// ---------------------------------------------------------------------------
#define GLDW 20
#define GARR (128 * GLDW)               // words per array
#define GSTG (2 * GARR)                 // words per stage (A + B)
#define GEMM_SMEM_BYTES (2 * GSTG * 4)  // 40960

template<int MODE>
__global__ __launch_bounds__(256, 2)
void gemm_fp16(const float* __restrict__ bias, float* __restrict__ C_out,
               int M, int N, int K)
{
    extern __shared__ uint32_t gsm[];

    const __half *A, *B;
    if (MODE == 0) { A = g_x;  B = g_wq; }
    else           { A = g_at; B = g_wo; }

    const int tid  = threadIdx.x;
    const int lane = tid & 31;
    const int warp = tid >> 5;
    const int wr = warp >> 1, wc = warp & 1;
    const int gid = lane >> 2, tig = lane & 3;

    const int bm = blockIdx.y * 128;
    const int bn = blockIdx.x * 128;

    const int lrow   = tid >> 2;          // 0..63
    const int lchunk = tid & 3;           // 16B chunk -> half offset lchunk*8

    const uint32_t sb = (uint32_t)__cvta_generic_to_shared(gsm);

    #define G_LOAD(T, S) do {                                                   \
        int k0_ = (T) * 32;                                                     \
        _Pragma("unroll")                                                       \
        for (int hh = 0; hh < 2; hh++) {                                        \
            int row = lrow + hh * 64;                                           \
            uint32_t d0 = sb + (uint32_t)((S)*GSTG + row*GLDW + lchunk*4) * 4;  \
            size_t asrc = (size_t)(bm + row) * K + k0_ + lchunk*8;              \
            size_t bsrc = (size_t)(bn + row) * K + k0_ + lchunk*8;              \
            asm volatile("cp.async.cg.shared.global [%0], [%1], 16;\n"          \
                :: "r"(d0),          "l"(A + asrc));                            \
            asm volatile("cp.async.cg.shared.global [%0], [%1], 16;\n"          \
                :: "r"(d0 + GARR*4), "l"(B + bsrc));                            \
        }                                                                       \
        asm volatile("cp.async.commit_group;\n");                               \
    } while (0)

    uint32_t a_off[2], b_off[4];
    #pragma unroll
    for (int mi = 0; mi < 2; mi++)
        a_off[mi] = (uint32_t)((wr*32 + mi*16 + (lane & 15)) * GLDW * 4
                               + (lane >> 4) * 16);
    #pragma unroll
    for (int np = 0; np < 4; np++)
        b_off[np] = (uint32_t)((wc*64 + np*16 + ((lane >> 4) & 1)*8 + (lane & 7))
                               * GLDW * 4 + ((lane >> 3) & 1) * 16);

    float acc[2][8][4] = {};

    const int nt = K / 32;
    G_LOAD(0, 0);

    for (int t = 0; t < nt; t++) {
        const int stg = t & 1;
        if (t + 1 < nt) {
            G_LOAD(t + 1, (t + 1) & 1);
            asm volatile("cp.async.wait_group 1;\n");
        } else {
            asm volatile("cp.async.wait_group 0;\n");
        }
        __syncthreads();

        const uint32_t sA = sb + (uint32_t)(stg * GSTG) * 4;
        const uint32_t sB = sA + GARR * 4;

        #pragma unroll
        for (int kcb = 0; kcb < 2; kcb++) {
            uint32_t ah[2][4];
            ldsm_x4(ah[0], sA + a_off[0] + kcb*32);
            ldsm_x4(ah[1], sA + a_off[1] + kcb*32);
            #pragma unroll
            for (int np = 0; np < 4; np++) {
                uint32_t bf[4];
                ldsm_x4(bf, sB + b_off[np] + kcb*32);
                #pragma unroll
                for (int sub = 0; sub < 2; sub++) {
                    #pragma unroll
                    for (int mi = 0; mi < 2; mi++) {
                        mma16816(acc[mi][np*2 + sub], ah[mi], bf + sub*2);
                    }
                }
            }
        }
        __syncthreads();
    }
    #undef G_LOAD

    // ---- Epilogue ----
    if (MODE == 1) {
        #pragma unroll
        for (int mi = 0; mi < 2; mi++) {
            int row = bm + wr * 32 + mi * 16 + gid;
            #pragma unroll
            for (int ni = 0; ni < 8; ni++) {
                int col = bn + wc * 64 + ni * 8 + tig * 2;
                float2 bv = *(const float2*)(bias + col);
                float2 v0 = make_float2(acc[mi][ni][0] + bv.x, acc[mi][ni][1] + bv.y);
                float2 v1 = make_float2(acc[mi][ni][2] + bv.x, acc[mi][ni][3] + bv.y);
                *(float2*)(C_out + (size_t)row * N + col)       = v0;
                *(float2*)(C_out + (size_t)(row + 8) * N + col) = v1;
            }
        }
    } else {
        // Fused qkv repack (fp16)
        #pragma unroll
        for (int mi = 0; mi < 2; mi++) {
            const int row  = bm + wr * 32 + mi * 16 + gid;
            const int bidx = row >> 11;
            const int tokA = row & 2047;
            const int tokB = tokA + 8;
            #pragma unroll
            for (int ni = 0; ni < 8; ni++) {
                int col = bn + wc * 64 + ni * 8 + tig * 2;
                int h   = col / 192;
                int r   = col - h * 192;
                int bh  = bidx * H_ + h;
                float v0 = acc[mi][ni][0], v1 = acc[mi][ni][1];
                float v2 = acc[mi][ni][2], v3 = acc[mi][ni][3];
                if (r < 128) {
                    __half* dh;
                    int d;
                    if (r < 64) {
                        d = r;
                        v0 *= (1.0f/HD_); v1 *= (1.0f/HD_);
                        v2 *= (1.0f/HD_); v3 *= (1.0f/HD_);
                        dh = g_aq;
                    } else {
                        d = r - 64;
                        dh = g_ak;
                    }
                    size_t i0 = ((size_t)bh * S_ + tokA) * HD_ + d;
                    size_t i1 = ((size_t)bh * S_ + tokB) * HD_ + d;
                    *(uint32_t*)(dh + i0) = pack_h2(v0, v1);
                    *(uint32_t*)(dh + i1) = pack_h2(v2, v3);
                } else {
                    int d = r - 128;
                    size_t r0 = ((size_t)bh * HD_ + d)     * S_;
                    size_t r1 = ((size_t)bh * HD_ + d + 1) * S_;
                    g_avt[r0 + tokA] = __float2half_rn(v0);
                    g_avt[r1 + tokA] = __float2half_rn(v1);
                    g_avt[r0 + tokB] = __float2half_rn(v2);
                    g_avt[r1 + tokB] = __float2half_rn(v3);
                }
            }
        }
    }
}

// ---------------------------------------------------------------------------
// fp16 tensor-core causal flash attention, LPT block order.
// K/V: 2 smem arrays per buffer (36 KB total -> 2 CTAs/SM).
// ---------------------------------------------------------------------------
#define ROW_W   36
#define ARR_W   (64 * ROW_W)
#define BUF_W   (2 * ARR_W)
#define ATTN_SMEM_BYTES (2 * BUF_W * 4)   // 36864

__global__ __launch_bounds__(256)
void attn_mma()
{
    extern __shared__ uint32_t smw[];
    const int tid  = threadIdx.x;
    const int w    = tid >> 5, lane = tid & 31;
    const int gid  = lane >> 2, tig = lane & 3;
    const int bx   = (int)(gridDim.y - 1 - blockIdx.y);   // LPT: heavy first
    const int bh   = blockIdx.x;
    const int b    = bh >> 4;
    const int h    = bh & 15;
    const int rA   = bx * 128 + w * 16 + gid;
    const int rB   = rA + 8;

    // Q fragments (fp16), loaded once. Row = 64 halfs = 32 words.
    const uint32_t* q_p = (const uint32_t*)(g_aq + ((size_t)bh * S_ + bx*128 + w*16) * HD_);
    uint32_t qh[4][4];
    #pragma unroll
    for (int kc = 0; kc < 4; kc++) {
        int w0 = 8*kc + tig;
        qh[kc][0] = q_p[ gid      * 32 + w0    ];
        qh[kc][1] = q_p[(gid + 8) * 32 + w0    ];
        qh[kc][2] = q_p[ gid      * 32 + w0 + 4];
        qh[kc][3] = q_p[(gid + 8) * 32 + w0 + 4];
    }

    float o[8][4] = {};
    float mA = -INFINITY, mB = -INFINITY, lA = 0.f, lB = 0.f;

    const __half* k_p = g_ak  + (size_t)bh * S_ * HD_;
    const __half* v_p = g_avt + (size_t)bh * HD_ * S_;

    const uint32_t sb = (uint32_t)__cvta_generic_to_shared(smw);
    const int lr  = tid >> 3;     // 0..31
    const int seg = tid & 7;

    const uint32_t frag_off = (uint32_t)((lane & 7) * ROW_W * 4 + (lane >> 3) * 16);

    #define LOAD_KV(T, BUF) do {                                                \
        _Pragma("unroll")                                                       \
        for (int i = 0; i < 4; i++) {                                           \
            int arr = i >> 1;                                                   \
            int r   = (i & 1) * 32 + lr;                                        \
            uint32_t dst = sb + ((BUF)*BUF_W + arr*ARR_W + r*ROW_W + seg*4)*4;  \
            const __half* srcp;                                                 \
            if (arr == 0) srcp = k_p + (size_t)((T)*64 + r) * HD_ + seg*8;      \
            else          srcp = v_p + (size_t)r * S_ + (T)*64 + seg*8;         \
            asm volatile("cp.async.cg.shared.global [%0], [%1], 16;\n"          \
                :: "r"(dst), "l"(srcp));                                        \
        }                                                                       \
        asm volatile("cp.async.commit_group;\n");                               \
    } while (0)

    const int nt = 2 * (bx + 1);
    LOAD_KV(0, 0);

    for (int t = 0; t < nt; t++) {
        const int buf = t & 1;
        if (t + 1 < nt) {
            LOAD_KV(t + 1, (t + 1) & 1);
            asm volatile("cp.async.wait_group 1;\n");
        } else {
            asm volatile("cp.async.wait_group 0;\n");
        }
        __syncthreads();

        const uint32_t sK = sb + (uint32_t)(buf * BUF_W) * 4;
        const uint32_t sV = sK + ARR_W * 4;

        // ---- S = Q @ K^T ----
        float s[8][4];
        #pragma unroll
        for (int ni = 0; ni < 8; ni++) { s[ni][0]=0; s[ni][1]=0; s[ni][2]=0; s[ni][3]=0; }
        #pragma unroll
        for (int ni = 0; ni < 8; ni++) {
            uint32_t off = (uint32_t)(ni * 8 * ROW_W * 4) + frag_off;
            #pragma unroll
            for (int kp = 0; kp < 2; kp++) {
                uint32_t k4[4];
                ldsm_x4(k4, sK + off + kp*64);
                mma16816(s[ni], qh[2*kp],   k4);
                mma16816(s[ni], qh[2*kp+1], k4 + 2);
            }
        }

        // ---- causal mask (only diagonal tiles) ----
        if (t >= 2 * bx) {
            #pragma unroll
            for (int ni = 0; ni < 8; ni++) {
                int c0 = t * 64 + ni * 8 + 2 * tig;
                if (c0     > rA) s[ni][0] = -1e30f;
                if (c0 + 1 > rA) s[ni][1] = -1e30f;
                if (c0     > rB) s[ni][2] = -1e30f;
                if (c0 + 1 > rB) s[ni][3] = -1e30f;
            }
        }

        // ---- online softmax ----
        float tmA = -INFINITY, tmB = -INFINITY;
        #pragma unroll
        for (int ni = 0; ni < 8; ni++) {
            tmA = fmaxf(tmA, fmaxf(s[ni][0], s[ni][1]));
            tmB = fmaxf(tmB, fmaxf(s[ni][2], s[ni][3]));
        }
        tmA = fmaxf(tmA, __shfl_xor_sync(0xffffffffu, tmA, 1));
        tmA = fmaxf(tmA, __shfl_xor_sync(0xffffffffu, tmA, 2));
        tmB = fmaxf(tmB, __shfl_xor_sync(0xffffffffu, tmB, 1));
        tmB = fmaxf(tmB, __shfl_xor_sync(0xffffffffu, tmB, 2));

        float mnA = fmaxf(mA, tmA), mnB = fmaxf(mB, tmB);
        float sfA = __expf(mA - mnA), sfB = __expf(mB - mnB);
        float lsA = 0.f, lsB = 0.f;

        uint32_t ph[4][4];
        #pragma unroll
        for (int ni = 0; ni < 8; ni++) {
            float e0 = __expf(s[ni][0] - mnA);
            float e1 = __expf(s[ni][1] - mnA);
            float e2 = __expf(s[ni][2] - mnB);
            float e3 = __expf(s[ni][3] - mnB);
            lsA += e0 + e1;  lsB += e2 + e3;
            int kc = ni >> 1, off = (ni & 1) * 2;
            ph[kc][off]     = pack_h2(e0, e1);
            ph[kc][off + 1] = pack_h2(e2, e3);
        }
        lsA += __shfl_xor_sync(0xffffffffu, lsA, 1);
        lsA += __shfl_xor_sync(0xffffffffu, lsA, 2);
        lsB += __shfl_xor_sync(0xffffffffu, lsB, 1);
        lsB += __shfl_xor_sync(0xffffffffu, lsB, 2);

        mA = mnA; mB = mnB;
        lA = lA * sfA + lsA;
        lB = lB * sfB + lsB;

        #pragma unroll
        for (int nd = 0; nd < 8; nd++) {
            o[nd][0] *= sfA; o[nd][1] *= sfA;
            o[nd][2] *= sfB; o[nd][3] *= sfB;
        }

        // ---- O += P @ V ----
        #pragma unroll
        for (int nd = 0; nd < 8; nd++) {
            uint32_t off = (uint32_t)(nd * 8 * ROW_W * 4) + frag_off;
            #pragma unroll
            for (int kp = 0; kp < 2; kp++) {
                uint32_t v4[4];
                ldsm_x4(v4, sV + off + kp*64);
                mma16816(o[nd], ph[2*kp],   v4);
                mma16816(o[nd], ph[2*kp+1], v4 + 2);
            }
        }
        __syncthreads();
    }
    #undef LOAD_KV

    // ---- epilogue: normalize, write fp16 g_at [B*S, 1024] ----
    const float iA = 1.0f / lA, iB = 1.0f / lB;
    const size_t gRowA = (size_t)(b * S_ + rA);
    const size_t gRowB = (size_t)(b * S_ + rB);
    #pragma unroll
    for (int nd = 0; nd < 8; nd++) {
        size_t i0 = gRowA * D_ + h * HD_ + nd * 8 + 2 * tig;
        size_t i1 = gRowB * D_ + h * HD_ + nd * 8 + 2 * tig;
        *(uint32_t*)(g_at + i0) = pack_h2(o[nd][0] * iA, o[nd][1] * iA);
        *(uint32_t*)(g_at + i1) = pack_h2(o[nd][2] * iB, o[nd][3] * iB);
    }
}

// ---------------------------------------------------------------------------
extern "C" void kernel_launch(void* const* d_in, const int* in_sizes, int n_in,
                              void* d_out, int out_size)
{
    const float* x = nullptr, *w_qkv = nullptr, *w_out = nullptr, *b_out = nullptr;
    for (int i = 0; i < n_in; i++) {
        long long n = in_sizes[i];
        if      (n == (long long)B_ * S_ * D_)      x     = (const float*)d_in[i];
        else if (n == (long long)N_QKV * D_)        w_qkv = (const float*)d_in[i];
        else if (n == (long long)D_ * D_)           w_out = (const float*)d_in[i];
        else if (n == (long long)D_)                b_out = (const float*)d_in[i];
        // mask ignored: causality is static
    }
    float* out = (float*)d_out;

    cudaFuncSetAttribute(attn_mma, cudaFuncAttributeMaxDynamicSharedMemorySize,
                         ATTN_SMEM_BYTES);
    cudaFuncSetAttribute(gemm_fp16<0>, cudaFuncAttributeMaxDynamicSharedMemorySize,
                         GEMM_SMEM_BYTES);
    cudaFuncSetAttribute(gemm_fp16<1>, cudaFuncAttributeMaxDynamicSharedMemorySize,
                         GEMM_SMEM_BYTES);

    // 0) Merged fp16 convert of x, w_qkv, w_out (one launch)
    cvt_all<<<2368, 256>>>(x, w_qkv, w_out);

    // 1) QKV projection + fused repack
    gemm_fp16<0><<<dim3(N_QKV / 128, M_TOT / 128), 256, GEMM_SMEM_BYTES>>>(
        nullptr, nullptr, M_TOT, N_QKV, D_);

    // 2) fp16 causal flash attention (LPT block order) -> g_at
    attn_mma<<<dim3(B_ * H_, S_ / 128), 256, ATTN_SMEM_BYTES>>>();

    // 3) Output projection: out = attn @ w_out^T + b_out
    gemm_fp16<1><<<dim3(D_ / 128, M_TOT / 128), 256, GEMM_SMEM_BYTES>>>(
        b_out, out, M_TOT, D_, D_);
}